// round 2
// baseline (speedup 1.0000x reference)
#include <cuda_runtime.h>
#include <cuda_bf16.h>
#include <math.h>

// Problem constants
#define BATCH 4
#define SEQ   512
#define DMODEL 768
#define FFDIM 3072
#define NHEAD 12
#define HDIM  64
#define NTOK  (BATCH*SEQ)          // 2048
#define NBLOCKS 12

// ---------------- scratch (device globals; no allocation allowed) -------------
__device__ float g_xln[NTOK * DMODEL];
__device__ float g_q  [NTOK * DMODEL];
__device__ float g_k  [NTOK * DMODEL];
__device__ float g_v  [NTOK * DMODEL];
__device__ float g_h1 [NTOK * FFDIM];

// ---------------- LayerNorm: one block per row ------------------------------
__global__ __launch_bounds__(256) void ln_kernel(
    const float* __restrict__ x, const float* __restrict__ g,
    const float* __restrict__ be, float* __restrict__ y)
{
    __shared__ float redS[8];
    __shared__ float redS2[8];
    const int r = blockIdx.x;
    const int tid = threadIdx.x;
    const float* xr = x + (size_t)r * DMODEL;

    float vals[3];
    float s = 0.f, s2 = 0.f;
#pragma unroll
    for (int c = 0; c < 3; c++) {
        float v = xr[tid + c * 256];
        vals[c] = v;
        s += v; s2 += v * v;
    }
#pragma unroll
    for (int o = 16; o > 0; o >>= 1) {
        s  += __shfl_xor_sync(0xffffffffu, s,  o);
        s2 += __shfl_xor_sync(0xffffffffu, s2, o);
    }
    const int wid = tid >> 5, lane = tid & 31;
    if (lane == 0) { redS[wid] = s; redS2[wid] = s2; }
    __syncthreads();
    if (tid < 32) {
        float a  = (tid < 8) ? redS [tid] : 0.f;
        float a2 = (tid < 8) ? redS2[tid] : 0.f;
#pragma unroll
        for (int o = 4; o > 0; o >>= 1) {
            a  += __shfl_xor_sync(0xffffffffu, a,  o);
            a2 += __shfl_xor_sync(0xffffffffu, a2, o);
        }
        if (tid == 0) { redS[0] = a; redS2[0] = a2; }
    }
    __syncthreads();
    const float mu  = redS[0]  * (1.f / DMODEL);
    const float var = redS2[0] * (1.f / DMODEL) - mu * mu;
    const float inv = rsqrtf(var + 1e-5f);
    float* yr = y + (size_t)r * DMODEL;
#pragma unroll
    for (int c = 0; c < 3; c++) {
        int j = tid + c * 256;
        yr[j] = (vals[c] - mu) * inv * g[j] + be[j];
    }
}

// ---------------- SGEMM: C[M,N] = act(A[M,K] @ B[K,N] + bias) ---------------
// MODE 0: store;  MODE 1: gelu(exact) then store;  MODE 2: C += (residual add)
// Tiles: 128x128x8, 256 threads, 8x8 per thread. All dims divisible.
template <int MODE>
__global__ __launch_bounds__(256) void sgemm_kernel(
    const float* __restrict__ A, const float* __restrict__ B,
    const float* __restrict__ bias, float* __restrict__ C,
    int M, int N, int K)
{
    __shared__ float As[8][128];
    __shared__ float Bs[8][128];

    const int tid = threadIdx.x;
    const int ty = tid >> 4;        // 0..15 -> row group
    const int tx = tid & 15;        // 0..15 -> col group
    const int rowBase = blockIdx.y * 128;
    const int colBase = blockIdx.x * 128;

    const int arow = tid >> 1;              // 0..127
    const int acol = (tid & 1) * 4;         // 0 or 4
    const int brow = tid >> 5;              // 0..7
    const int bcol = (tid & 31) * 4;        // 0..124

    const float* Aptr = A + (size_t)(rowBase + arow) * K + acol;
    const float* Bptr = B + (size_t)brow * N + colBase + bcol;

    float acc[8][8];
#pragma unroll
    for (int i = 0; i < 8; i++)
#pragma unroll
        for (int j = 0; j < 8; j++) acc[i][j] = 0.f;

    for (int k0 = 0; k0 < K; k0 += 8) {
        float4 av = *(const float4*)(Aptr + k0);
        As[acol + 0][arow] = av.x;
        As[acol + 1][arow] = av.y;
        As[acol + 2][arow] = av.z;
        As[acol + 3][arow] = av.w;
        float4 bv = *(const float4*)(Bptr + (size_t)k0 * N);
        *(float4*)&Bs[brow][bcol] = bv;
        __syncthreads();

#pragma unroll
        for (int kk = 0; kk < 8; kk++) {
            float4 a0 = *(const float4*)&As[kk][ty * 8];
            float4 a1 = *(const float4*)&As[kk][ty * 8 + 4];
            float4 b0 = *(const float4*)&Bs[kk][tx * 8];
            float4 b1 = *(const float4*)&Bs[kk][tx * 8 + 4];
            float ar[8] = {a0.x,a0.y,a0.z,a0.w,a1.x,a1.y,a1.z,a1.w};
            float br[8] = {b0.x,b0.y,b0.z,b0.w,b1.x,b1.y,b1.z,b1.w};
#pragma unroll
            for (int i = 0; i < 8; i++)
#pragma unroll
                for (int j = 0; j < 8; j++)
                    acc[i][j] = fmaf(ar[i], br[j], acc[i][j]);
        }
        __syncthreads();
    }

    const int row0 = rowBase + ty * 8;
    const int col0 = colBase + tx * 8;
    float bb[8];
#pragma unroll
    for (int j = 0; j < 8; j++) bb[j] = bias[col0 + j];

#pragma unroll
    for (int i = 0; i < 8; i++) {
        float* Crow = C + (size_t)(row0 + i) * N + col0;
#pragma unroll
        for (int j = 0; j < 8; j++) {
            float v = acc[i][j] + bb[j];
            if (MODE == 1) {
                v = 0.5f * v * (1.0f + erff(v * 0.70710678118654752f));
            }
            if (MODE == 2) Crow[j] += v;
            else           Crow[j] = v;
        }
    }
}

// ---------------- Fused attention ------------------------------------------
// grid (8 q-tiles, 48 batch-heads), 256 threads.
// Per CTA: Q tile [64,64], loop K tiles -> S[64,512] in smem, exact softmax,
// then O = P @ V, added into residual x.
#define QS_LD 65
#define S_LD  513
#define ATTN_SMEM_FLOATS (2 * 64 * QS_LD + 64 * S_LD)
#define ATTN_SMEM_BYTES  (ATTN_SMEM_FLOATS * 4)

__global__ __launch_bounds__(256) void attn_kernel(
    const float* __restrict__ q, const float* __restrict__ k,
    const float* __restrict__ v, float* __restrict__ x)
{
    extern __shared__ float sm[];
    float* Qs = sm;                       // [64][65]
    float* Ks = sm + 64 * QS_LD;          // [64][65]  (reused for V)
    float* S  = sm + 2 * 64 * QS_LD;      // [64][513]

    const int tid = threadIdx.x;
    const int qt = blockIdx.x;
    const int bh = blockIdx.y;
    const int b = bh / NHEAD, h = bh % NHEAD;

    const float* qb = q + ((size_t)b * SEQ + qt * 64) * DMODEL + h * HDIM;
    const float* kb = k + (size_t)b * SEQ * DMODEL + h * HDIM;
    const float* vb = v + (size_t)b * SEQ * DMODEL + h * HDIM;

    // load Q tile (64x64)
#pragma unroll
    for (int c = 0; c < 4; c++) {
        int fi = tid + c * 256;          // float4 id, 1024 total
        int row = fi >> 4, col4 = fi & 15;
        float4 t = *(const float4*)(qb + (size_t)row * DMODEL + col4 * 4);
        float* d = Qs + row * QS_LD + col4 * 4;
        d[0] = t.x; d[1] = t.y; d[2] = t.z; d[3] = t.w;
    }

    const int ty = tid >> 4, tx = tid & 15;

    // --- S = (Q @ K^T) * 1/sqrt(hd) ---
    for (int kt = 0; kt < 8; kt++) {
        __syncthreads();
#pragma unroll
        for (int c = 0; c < 4; c++) {
            int fi = tid + c * 256;
            int row = fi >> 4, col4 = fi & 15;
            float4 t = *(const float4*)(kb + (size_t)(kt * 64 + row) * DMODEL + col4 * 4);
            float* d = Ks + row * QS_LD + col4 * 4;
            d[0] = t.x; d[1] = t.y; d[2] = t.z; d[3] = t.w;
        }
        __syncthreads();

        float acc[4][4];
#pragma unroll
        for (int i = 0; i < 4; i++)
#pragma unroll
            for (int j = 0; j < 4; j++) acc[i][j] = 0.f;

#pragma unroll
        for (int dd = 0; dd < 64; dd++) {
            float a[4], bbv[4];
#pragma unroll
            for (int i = 0; i < 4; i++) a[i]   = Qs[(ty * 4 + i) * QS_LD + dd];
#pragma unroll
            for (int j = 0; j < 4; j++) bbv[j] = Ks[(tx * 4 + j) * QS_LD + dd];
#pragma unroll
            for (int i = 0; i < 4; i++)
#pragma unroll
                for (int j = 0; j < 4; j++)
                    acc[i][j] = fmaf(a[i], bbv[j], acc[i][j]);
        }
#pragma unroll
        for (int i = 0; i < 4; i++)
#pragma unroll
            for (int j = 0; j < 4; j++)
                S[(ty * 4 + i) * S_LD + kt * 64 + tx * 4 + j] = acc[i][j] * 0.125f;
    }
    __syncthreads();

    // --- softmax rows (warp per row, 8 rows per warp) ---
    const int wid = tid >> 5, lane = tid & 31;
    for (int rr = 0; rr < 8; rr++) {
        float* Sr = S + (wid * 8 + rr) * S_LD;
        float m = -1e30f;
        for (int j = lane; j < SEQ; j += 32) m = fmaxf(m, Sr[j]);
#pragma unroll
        for (int o = 16; o > 0; o >>= 1) m = fmaxf(m, __shfl_xor_sync(0xffffffffu, m, o));
        float s = 0.f;
        for (int j = lane; j < SEQ; j += 32) {
            float e = __expf(Sr[j] - m);
            Sr[j] = e;
            s += e;
        }
#pragma unroll
        for (int o = 16; o > 0; o >>= 1) s += __shfl_xor_sync(0xffffffffu, s, o);
        float inv = 1.f / s;
        for (int j = lane; j < SEQ; j += 32) Sr[j] *= inv;
    }

    // --- O = P @ V ---
    float acc[4][4];
#pragma unroll
    for (int i = 0; i < 4; i++)
#pragma unroll
        for (int j = 0; j < 4; j++) acc[i][j] = 0.f;

    for (int kt = 0; kt < 8; kt++) {
        __syncthreads();
#pragma unroll
        for (int c = 0; c < 4; c++) {
            int fi = tid + c * 256;
            int row = fi >> 4, col4 = fi & 15;
            float4 t = *(const float4*)(vb + (size_t)(kt * 64 + row) * DMODEL + col4 * 4);
            float* d = Ks + row * QS_LD + col4 * 4;
            d[0] = t.x; d[1] = t.y; d[2] = t.z; d[3] = t.w;
        }
        __syncthreads();

#pragma unroll
        for (int kk = 0; kk < 64; kk++) {
            float a[4], bbv[4];
#pragma unroll
            for (int i = 0; i < 4; i++) a[i]   = S[(ty * 4 + i) * S_LD + kt * 64 + kk];
#pragma unroll
            for (int j = 0; j < 4; j++) bbv[j] = Ks[kk * QS_LD + tx * 4 + j];
#pragma unroll
            for (int i = 0; i < 4; i++)
#pragma unroll
                for (int j = 0; j < 4; j++)
                    acc[i][j] = fmaf(a[i], bbv[j], acc[i][j]);
        }
    }

    // residual add into x (unique writer per element)
    float* xb = x + ((size_t)b * SEQ + qt * 64) * DMODEL + h * HDIM;
#pragma unroll
    for (int i = 0; i < 4; i++)
#pragma unroll
        for (int j = 0; j < 4; j++)
            xb[(size_t)(ty * 4 + i) * DMODEL + tx * 4 + j] += acc[i][j];
}

// ---------------- launch ----------------------------------------------------
extern "C" void kernel_launch(void* const* d_in, const int* in_sizes, int n_in,
                              void* d_out, int out_size)
{
    const float* x_in = (const float*)d_in[0];
    const float* Wq = (const float*)d_in[1];
    const float* bq = (const float*)d_in[2];
    const float* Wk = (const float*)d_in[3];
    const float* bk = (const float*)d_in[4];
    const float* Wv = (const float*)d_in[5];
    const float* bv = (const float*)d_in[6];
    const float* g1 = (const float*)d_in[7];
    const float* be1 = (const float*)d_in[8];
    const float* g2 = (const float*)d_in[9];
    const float* be2 = (const float*)d_in[10];
    const float* W0 = (const float*)d_in[11];
    const float* b0 = (const float*)d_in[12];
    const float* W1 = (const float*)d_in[13];
    const float* b1 = (const float*)d_in[14];

    float* x = (float*)d_out;

    void *p_xln, *p_q, *p_k, *p_v, *p_h1;
    cudaGetSymbolAddress(&p_xln, g_xln);
    cudaGetSymbolAddress(&p_q, g_q);
    cudaGetSymbolAddress(&p_k, g_k);
    cudaGetSymbolAddress(&p_v, g_v);
    cudaGetSymbolAddress(&p_h1, g_h1);
    float* xln = (float*)p_xln;
    float* q = (float*)p_q;
    float* k = (float*)p_k;
    float* v = (float*)p_v;
    float* h1 = (float*)p_h1;

    cudaFuncSetAttribute(attn_kernel, cudaFuncAttributeMaxDynamicSharedMemorySize,
                         ATTN_SMEM_BYTES);

    // x = input
    cudaMemcpyAsync(x, x_in, (size_t)NTOK * DMODEL * sizeof(float),
                    cudaMemcpyDeviceToDevice, 0);

    const dim3 gemmQKV(DMODEL / 128, NTOK / 128);   // (6,16)
    const dim3 gemmFF1(FFDIM / 128, NTOK / 128);    // (24,16)
    const dim3 gemmFF2(DMODEL / 128, NTOK / 128);   // (6,16)
    const dim3 attnGrid(SEQ / 64, BATCH * NHEAD);   // (8,48)

    for (int blk = 0; blk < NBLOCKS; blk++) {
        ln_kernel<<<NTOK, 256>>>(x, g1, be1, xln);
        sgemm_kernel<0><<<gemmQKV, 256>>>(xln, Wq, bq, q, NTOK, DMODEL, DMODEL);
        sgemm_kernel<0><<<gemmQKV, 256>>>(xln, Wk, bk, k, NTOK, DMODEL, DMODEL);
        sgemm_kernel<0><<<gemmQKV, 256>>>(xln, Wv, bv, v, NTOK, DMODEL, DMODEL);
        attn_kernel<<<attnGrid, 256, ATTN_SMEM_BYTES>>>(q, k, v, x);
        ln_kernel<<<NTOK, 256>>>(x, g2, be2, xln);
        sgemm_kernel<1><<<gemmFF1, 256>>>(xln, W0, b0, h1, NTOK, FFDIM, DMODEL);
        sgemm_kernel<2><<<gemmFF2, 256>>>(h1, W1, b1, x, NTOK, DMODEL, FFDIM);
    }
}

// round 3
// speedup vs baseline: 2.6664x; 2.6664x over previous
#include <cuda_runtime.h>
#include <cuda_bf16.h>
#include <math.h>

// Problem constants
#define BATCH 4
#define SEQ   512
#define DMODEL 768
#define FFDIM 3072
#define NHEAD 12
#define HDIM  64
#define NTOK  (BATCH*SEQ)          // 2048
#define NBLOCKS 12

// ---------------- scratch (device globals; no allocation allowed) -------------
__device__ float g_xln[NTOK * DMODEL];
__device__ float g_q  [NTOK * DMODEL];
__device__ float g_k  [NTOK * DMODEL];
__device__ float g_v  [NTOK * DMODEL];
__device__ float g_h1 [NTOK * FFDIM];

// ---------------- LayerNorm: one block per row ------------------------------
__global__ __launch_bounds__(256) void ln_kernel(
    const float* __restrict__ x, const float* __restrict__ g,
    const float* __restrict__ be, float* __restrict__ y)
{
    __shared__ float redS[8];
    __shared__ float redS2[8];
    const int r = blockIdx.x;
    const int tid = threadIdx.x;
    const float* xr = x + (size_t)r * DMODEL;

    float vals[3];
    float s = 0.f, s2 = 0.f;
#pragma unroll
    for (int c = 0; c < 3; c++) {
        float v = xr[tid + c * 256];
        vals[c] = v;
        s += v; s2 += v * v;
    }
#pragma unroll
    for (int o = 16; o > 0; o >>= 1) {
        s  += __shfl_xor_sync(0xffffffffu, s,  o);
        s2 += __shfl_xor_sync(0xffffffffu, s2, o);
    }
    const int wid = tid >> 5, lane = tid & 31;
    if (lane == 0) { redS[wid] = s; redS2[wid] = s2; }
    __syncthreads();
    if (tid < 32) {
        float a  = (tid < 8) ? redS [tid] : 0.f;
        float a2 = (tid < 8) ? redS2[tid] : 0.f;
#pragma unroll
        for (int o = 4; o > 0; o >>= 1) {
            a  += __shfl_xor_sync(0xffffffffu, a,  o);
            a2 += __shfl_xor_sync(0xffffffffu, a2, o);
        }
        if (tid == 0) { redS[0] = a; redS2[0] = a2; }
    }
    __syncthreads();
    const float mu  = redS[0]  * (1.f / DMODEL);
    const float var = redS2[0] * (1.f / DMODEL) - mu * mu;
    const float inv = rsqrtf(var + 1e-5f);
    float* yr = y + (size_t)r * DMODEL;
#pragma unroll
    for (int c = 0; c < 3; c++) {
        int j = tid + c * 256;
        yr[j] = (vals[c] - mu) * inv * g[j] + be[j];
    }
}

// ======================= TF32 tensor-core GEMM ==============================
// C[M,N] = act(A[M,K] @ B[K,N] + bias)
// CTA tile 128x128xBK16, 8 warps (2x4), warp tile 64x32, mma m16n8k8 tf32.
// MODE 0: store; MODE 1: exact gelu; MODE 2: C += v (residual accumulate)

#define BM 128
#define BN 128
#define BK 16
#define AS_LD 17     // floats per As row (pad)
#define BS_LD 136    // floats per Bs row (pad 8 -> conflict-free frag reads)

__device__ __forceinline__ unsigned f2tf32(float f) {
    unsigned r;
    asm("cvt.rna.tf32.f32 %0, %1;" : "=r"(r) : "f"(f));
    return r;
}

template <int MODE>
__device__ __forceinline__ void tf32_gemm_core(
    const float* __restrict__ A, const float* __restrict__ B,
    const float* __restrict__ bias, float* __restrict__ C,
    int N, int K)
{
    __shared__ unsigned As[BM * AS_LD];   // As[row][k]
    __shared__ unsigned Bs[BK * BS_LD];   // Bs[k][col]

    const int tid  = threadIdx.x;
    const int lane = tid & 31;
    const int wid  = tid >> 5;
    const int wm   = wid >> 2;            // 0..1
    const int wn   = wid & 3;             // 0..3
    const int rowBase = blockIdx.y * BM;
    const int colBase = blockIdx.x * BN;

    // gmem load mapping
    const int aRow = tid >> 1;            // 0..127 (2 float4 per row of 16)
    const int aC4  = (tid & 1) * 2;       // float4 index 0/1 within first half
    // Each thread loads 2 float4 of A: (aRow, aC4) and (aRow, aC4+1)? simpler:
    // fi scheme below.

    float4 aPre[2], bPre[2];

    // --- helpers to load/store one BK-chunk ---
    auto loadA = [&](int k0, float4* dst) {
#pragma unroll
        for (int i = 0; i < 2; i++) {
            int fi = tid + i * 256;            // 512 float4 = 128x16
            int r = fi >> 2, c4 = fi & 3;
            dst[i] = *(const float4*)(A + (size_t)(rowBase + r) * K + k0 + c4 * 4);
        }
    };
    auto loadB = [&](int k0, float4* dst) {
#pragma unroll
        for (int i = 0; i < 2; i++) {
            int fi = tid + i * 256;            // 512 float4 = 16x128
            int r = fi >> 5, c4 = fi & 31;
            dst[i] = *(const float4*)(B + (size_t)(k0 + r) * N + colBase + c4 * 4);
        }
    };
    auto storeA = [&](const float4* src) {
#pragma unroll
        for (int i = 0; i < 2; i++) {
            int fi = tid + i * 256;
            int r = fi >> 2, c4 = fi & 3;
            unsigned* d = As + r * AS_LD + c4 * 4;
            d[0] = f2tf32(src[i].x); d[1] = f2tf32(src[i].y);
            d[2] = f2tf32(src[i].z); d[3] = f2tf32(src[i].w);
        }
    };
    auto storeB = [&](const float4* src) {
#pragma unroll
        for (int i = 0; i < 2; i++) {
            int fi = tid + i * 256;
            int r = fi >> 5, c4 = fi & 31;
            unsigned* d = Bs + r * BS_LD + c4 * 4;
            d[0] = f2tf32(src[i].x); d[1] = f2tf32(src[i].y);
            d[2] = f2tf32(src[i].z); d[3] = f2tf32(src[i].w);
        }
    };

    float acc[4][4][4];
#pragma unroll
    for (int i = 0; i < 4; i++)
#pragma unroll
        for (int j = 0; j < 4; j++)
#pragma unroll
            for (int t = 0; t < 4; t++) acc[i][j][t] = 0.f;

    // first chunk
    loadA(0, aPre); loadB(0, bPre);
    storeA(aPre); storeB(bPre);
    __syncthreads();

    const int lq = lane >> 2;   // lane/4
    const int lr = lane & 3;    // lane%4

    for (int k0 = BK; k0 <= K; k0 += BK) {
        const bool last = (k0 == K);
        if (!last) { loadA(k0, aPre); loadB(k0, bPre); }

        // compute current chunk: 2 k8 steps
#pragma unroll
        for (int s = 0; s < 2; s++) {
            unsigned af[4][4];
#pragma unroll
            for (int mt = 0; mt < 4; mt++) {
                int r0 = wm * 64 + mt * 16 + lq;
                int kc = s * 8 + lr;
                af[mt][0] = As[(r0    ) * AS_LD + kc    ];
                af[mt][1] = As[(r0 + 8) * AS_LD + kc    ];
                af[mt][2] = As[(r0    ) * AS_LD + kc + 4];
                af[mt][3] = As[(r0 + 8) * AS_LD + kc + 4];
            }
            unsigned bf[4][2];
#pragma unroll
            for (int nt = 0; nt < 4; nt++) {
                int c = wn * 32 + nt * 8 + lq;
                int kr = s * 8 + lr;
                bf[nt][0] = Bs[(kr    ) * BS_LD + c];
                bf[nt][1] = Bs[(kr + 4) * BS_LD + c];
            }
#pragma unroll
            for (int mt = 0; mt < 4; mt++)
#pragma unroll
                for (int nt = 0; nt < 4; nt++) {
                    asm volatile(
                        "mma.sync.aligned.m16n8k8.row.col.f32.tf32.tf32.f32 "
                        "{%0,%1,%2,%3}, {%4,%5,%6,%7}, {%8,%9}, {%0,%1,%2,%3};"
                        : "+f"(acc[mt][nt][0]), "+f"(acc[mt][nt][1]),
                          "+f"(acc[mt][nt][2]), "+f"(acc[mt][nt][3])
                        : "r"(af[mt][0]), "r"(af[mt][1]),
                          "r"(af[mt][2]), "r"(af[mt][3]),
                          "r"(bf[nt][0]), "r"(bf[nt][1]));
                }
        }

        if (!last) {
            __syncthreads();
            storeA(aPre); storeB(bPre);
            __syncthreads();
        }
    }

    // epilogue
#pragma unroll
    for (int mt = 0; mt < 4; mt++) {
        int row = rowBase + wm * 64 + mt * 16 + lq;
#pragma unroll
        for (int nt = 0; nt < 4; nt++) {
            int col = colBase + wn * 32 + nt * 8 + lr * 2;
            float b0 = bias[col], b1 = bias[col + 1];
            float v00 = acc[mt][nt][0] + b0;
            float v01 = acc[mt][nt][1] + b1;
            float v10 = acc[mt][nt][2] + b0;
            float v11 = acc[mt][nt][3] + b1;
            if (MODE == 1) {
                v00 = 0.5f * v00 * (1.0f + erff(v00 * 0.70710678118654752f));
                v01 = 0.5f * v01 * (1.0f + erff(v01 * 0.70710678118654752f));
                v10 = 0.5f * v10 * (1.0f + erff(v10 * 0.70710678118654752f));
                v11 = 0.5f * v11 * (1.0f + erff(v11 * 0.70710678118654752f));
            }
            float* C0 = C + (size_t)row * N + col;
            float* C1 = C + (size_t)(row + 8) * N + col;
            if (MODE == 2) {
                C0[0] += v00; C0[1] += v01;
                C1[0] += v10; C1[1] += v11;
            } else {
                C0[0] = v00; C0[1] = v01;
                C1[0] = v10; C1[1] = v11;
            }
        }
    }
}

template <int MODE>
__global__ __launch_bounds__(256) void tf32_gemm_kernel(
    const float* __restrict__ A, const float* __restrict__ B,
    const float* __restrict__ bias, float* __restrict__ C,
    int N, int K)
{
    tf32_gemm_core<MODE>(A, B, bias, C, N, K);
}

// Fused QKV: blockIdx.z selects which of the 3 projections this CTA computes.
__global__ __launch_bounds__(256) void tf32_gemm_qkv_kernel(
    const float* __restrict__ A,
    const float* __restrict__ Wq, const float* __restrict__ Wk, const float* __restrict__ Wv,
    const float* __restrict__ bq, const float* __restrict__ bk, const float* __restrict__ bv,
    float* __restrict__ q, float* __restrict__ k, float* __restrict__ v)
{
    const float* B; const float* bias; float* C;
    if (blockIdx.z == 0)      { B = Wq; bias = bq; C = q; }
    else if (blockIdx.z == 1) { B = Wk; bias = bk; C = k; }
    else                      { B = Wv; bias = bv; C = v; }
    tf32_gemm_core<0>(A, B, bias, C, DMODEL, DMODEL);
}

// ---------------- Fused attention (unchanged this round) --------------------
#define QS_LD 65
#define S_LD  513
#define ATTN_SMEM_FLOATS (2 * 64 * QS_LD + 64 * S_LD)
#define ATTN_SMEM_BYTES  (ATTN_SMEM_FLOATS * 4)

__global__ __launch_bounds__(256) void attn_kernel(
    const float* __restrict__ q, const float* __restrict__ k,
    const float* __restrict__ v, float* __restrict__ x)
{
    extern __shared__ float sm[];
    float* Qs = sm;                       // [64][65]
    float* Ks = sm + 64 * QS_LD;          // [64][65]  (reused for V)
    float* S  = sm + 2 * 64 * QS_LD;      // [64][513]

    const int tid = threadIdx.x;
    const int qt = blockIdx.x;
    const int bh = blockIdx.y;
    const int b = bh / NHEAD, h = bh % NHEAD;

    const float* qb = q + ((size_t)b * SEQ + qt * 64) * DMODEL + h * HDIM;
    const float* kb = k + (size_t)b * SEQ * DMODEL + h * HDIM;
    const float* vb = v + (size_t)b * SEQ * DMODEL + h * HDIM;

#pragma unroll
    for (int c = 0; c < 4; c++) {
        int fi = tid + c * 256;
        int row = fi >> 4, col4 = fi & 15;
        float4 t = *(const float4*)(qb + (size_t)row * DMODEL + col4 * 4);
        float* d = Qs + row * QS_LD + col4 * 4;
        d[0] = t.x; d[1] = t.y; d[2] = t.z; d[3] = t.w;
    }

    const int ty = tid >> 4, tx = tid & 15;

    for (int kt = 0; kt < 8; kt++) {
        __syncthreads();
#pragma unroll
        for (int c = 0; c < 4; c++) {
            int fi = tid + c * 256;
            int row = fi >> 4, col4 = fi & 15;
            float4 t = *(const float4*)(kb + (size_t)(kt * 64 + row) * DMODEL + col4 * 4);
            float* d = Ks + row * QS_LD + col4 * 4;
            d[0] = t.x; d[1] = t.y; d[2] = t.z; d[3] = t.w;
        }
        __syncthreads();

        float acc[4][4];
#pragma unroll
        for (int i = 0; i < 4; i++)
#pragma unroll
            for (int j = 0; j < 4; j++) acc[i][j] = 0.f;

#pragma unroll
        for (int dd = 0; dd < 64; dd++) {
            float a[4], bbv[4];
#pragma unroll
            for (int i = 0; i < 4; i++) a[i]   = Qs[(ty * 4 + i) * QS_LD + dd];
#pragma unroll
            for (int j = 0; j < 4; j++) bbv[j] = Ks[(tx * 4 + j) * QS_LD + dd];
#pragma unroll
            for (int i = 0; i < 4; i++)
#pragma unroll
                for (int j = 0; j < 4; j++)
                    acc[i][j] = fmaf(a[i], bbv[j], acc[i][j]);
        }
#pragma unroll
        for (int i = 0; i < 4; i++)
#pragma unroll
            for (int j = 0; j < 4; j++)
                S[(ty * 4 + i) * S_LD + kt * 64 + tx * 4 + j] = acc[i][j] * 0.125f;
    }
    __syncthreads();

    const int wid = tid >> 5, lane = tid & 31;
    for (int rr = 0; rr < 8; rr++) {
        float* Sr = S + (wid * 8 + rr) * S_LD;
        float m = -1e30f;
        for (int j = lane; j < SEQ; j += 32) m = fmaxf(m, Sr[j]);
#pragma unroll
        for (int o = 16; o > 0; o >>= 1) m = fmaxf(m, __shfl_xor_sync(0xffffffffu, m, o));
        float s = 0.f;
        for (int j = lane; j < SEQ; j += 32) {
            float e = __expf(Sr[j] - m);
            Sr[j] = e;
            s += e;
        }
#pragma unroll
        for (int o = 16; o > 0; o >>= 1) s += __shfl_xor_sync(0xffffffffu, s, o);
        float inv = 1.f / s;
        for (int j = lane; j < SEQ; j += 32) Sr[j] *= inv;
    }

    float acc[4][4];
#pragma unroll
    for (int i = 0; i < 4; i++)
#pragma unroll
        for (int j = 0; j < 4; j++) acc[i][j] = 0.f;

    for (int kt = 0; kt < 8; kt++) {
        __syncthreads();
#pragma unroll
        for (int c = 0; c < 4; c++) {
            int fi = tid + c * 256;
            int row = fi >> 4, col4 = fi & 15;
            float4 t = *(const float4*)(vb + (size_t)(kt * 64 + row) * DMODEL + col4 * 4);
            float* d = Ks + row * QS_LD + col4 * 4;
            d[0] = t.x; d[1] = t.y; d[2] = t.z; d[3] = t.w;
        }
        __syncthreads();

#pragma unroll
        for (int kk = 0; kk < 64; kk++) {
            float a[4], bbv[4];
#pragma unroll
            for (int i = 0; i < 4; i++) a[i]   = S[(ty * 4 + i) * S_LD + kt * 64 + kk];
#pragma unroll
            for (int j = 0; j < 4; j++) bbv[j] = Ks[kk * QS_LD + tx * 4 + j];
#pragma unroll
            for (int i = 0; i < 4; i++)
#pragma unroll
                for (int j = 0; j < 4; j++)
                    acc[i][j] = fmaf(a[i], bbv[j], acc[i][j]);
        }
    }

    float* xb = x + ((size_t)b * SEQ + qt * 64) * DMODEL + h * HDIM;
#pragma unroll
    for (int i = 0; i < 4; i++)
#pragma unroll
        for (int j = 0; j < 4; j++)
            xb[(size_t)(ty * 4 + i) * DMODEL + tx * 4 + j] += acc[i][j];
}

// ---------------- launch ----------------------------------------------------
extern "C" void kernel_launch(void* const* d_in, const int* in_sizes, int n_in,
                              void* d_out, int out_size)
{
    const float* x_in = (const float*)d_in[0];
    const float* Wq = (const float*)d_in[1];
    const float* bq = (const float*)d_in[2];
    const float* Wk = (const float*)d_in[3];
    const float* bk = (const float*)d_in[4];
    const float* Wv = (const float*)d_in[5];
    const float* bv = (const float*)d_in[6];
    const float* g1 = (const float*)d_in[7];
    const float* be1 = (const float*)d_in[8];
    const float* g2 = (const float*)d_in[9];
    const float* be2 = (const float*)d_in[10];
    const float* W0 = (const float*)d_in[11];
    const float* b0 = (const float*)d_in[12];
    const float* W1 = (const float*)d_in[13];
    const float* b1 = (const float*)d_in[14];

    float* x = (float*)d_out;

    void *p_xln, *p_q, *p_k, *p_v, *p_h1;
    cudaGetSymbolAddress(&p_xln, g_xln);
    cudaGetSymbolAddress(&p_q, g_q);
    cudaGetSymbolAddress(&p_k, g_k);
    cudaGetSymbolAddress(&p_v, g_v);
    cudaGetSymbolAddress(&p_h1, g_h1);
    float* xln = (float*)p_xln;
    float* q = (float*)p_q;
    float* k = (float*)p_k;
    float* v = (float*)p_v;
    float* h1 = (float*)p_h1;

    cudaFuncSetAttribute(attn_kernel, cudaFuncAttributeMaxDynamicSharedMemorySize,
                         ATTN_SMEM_BYTES);

    cudaMemcpyAsync(x, x_in, (size_t)NTOK * DMODEL * sizeof(float),
                    cudaMemcpyDeviceToDevice, 0);

    const dim3 gemmQKV(DMODEL / BN, NTOK / BM, 3);  // (6,16,3)
    const dim3 gemmFF1(FFDIM / BN, NTOK / BM);      // (24,16)
    const dim3 gemmFF2(DMODEL / BN, NTOK / BM);     // (6,16)
    const dim3 attnGrid(SEQ / 64, BATCH * NHEAD);   // (8,48)

    for (int blk = 0; blk < NBLOCKS; blk++) {
        ln_kernel<<<NTOK, 256>>>(x, g1, be1, xln);
        tf32_gemm_qkv_kernel<<<gemmQKV, 256>>>(xln, Wq, Wk, Wv, bq, bk, bv, q, k, v);
        attn_kernel<<<attnGrid, 256, ATTN_SMEM_BYTES>>>(q, k, v, x);
        ln_kernel<<<NTOK, 256>>>(x, g2, be2, xln);
        tf32_gemm_kernel<1><<<gemmFF1, 256>>>(xln, W0, b0, h1, FFDIM, DMODEL);
        tf32_gemm_kernel<2><<<gemmFF2, 256>>>(h1, W1, b1, x, DMODEL, FFDIM);
    }
}

// round 4
// speedup vs baseline: 3.3384x; 1.2520x over previous
#include <cuda_runtime.h>
#include <cuda_bf16.h>
#include <math.h>

// Problem constants
#define BATCH 4
#define SEQ   512
#define DMODEL 768
#define FFDIM 3072
#define NHEAD 12
#define HDIM  64
#define NTOK  (BATCH*SEQ)          // 2048
#define NBLOCKS 12

// ---------------- scratch (device globals; no allocation allowed) -----------
__device__ float g_xln[NTOK * DMODEL];
__device__ float g_q  [NTOK * DMODEL];
__device__ float g_k  [NTOK * DMODEL];
__device__ float g_v  [NTOK * DMODEL];
__device__ float g_h1 [NTOK * FFDIM];

__device__ __forceinline__ unsigned f2tf32(float f) {
    unsigned r;
    asm("cvt.rna.tf32.f32 %0, %1;" : "=r"(r) : "f"(f));
    return r;
}

// ---------------- LayerNorm: one block per row ------------------------------
__global__ __launch_bounds__(256) void ln_kernel(
    const float* __restrict__ x, const float* __restrict__ g,
    const float* __restrict__ be, float* __restrict__ y)
{
    __shared__ float redS[8];
    __shared__ float redS2[8];
    const int r = blockIdx.x;
    const int tid = threadIdx.x;
    const float* xr = x + (size_t)r * DMODEL;

    float vals[3];
    float s = 0.f, s2 = 0.f;
#pragma unroll
    for (int c = 0; c < 3; c++) {
        float v = xr[tid + c * 256];
        vals[c] = v;
        s += v; s2 += v * v;
    }
#pragma unroll
    for (int o = 16; o > 0; o >>= 1) {
        s  += __shfl_xor_sync(0xffffffffu, s,  o);
        s2 += __shfl_xor_sync(0xffffffffu, s2, o);
    }
    const int wid = tid >> 5, lane = tid & 31;
    if (lane == 0) { redS[wid] = s; redS2[wid] = s2; }
    __syncthreads();
    if (tid < 32) {
        float a  = (tid < 8) ? redS [tid] : 0.f;
        float a2 = (tid < 8) ? redS2[tid] : 0.f;
#pragma unroll
        for (int o = 4; o > 0; o >>= 1) {
            a  += __shfl_xor_sync(0xffffffffu, a,  o);
            a2 += __shfl_xor_sync(0xffffffffu, a2, o);
        }
        if (tid == 0) { redS[0] = a; redS2[0] = a2; }
    }
    __syncthreads();
    const float mu  = redS[0]  * (1.f / DMODEL);
    const float var = redS2[0] * (1.f / DMODEL) - mu * mu;
    const float inv = rsqrtf(var + 1e-5f);
    float* yr = y + (size_t)r * DMODEL;
#pragma unroll
    for (int c = 0; c < 3; c++) {
        int j = tid + c * 256;
        yr[j] = (vals[c] - mu) * inv * g[j] + be[j];
    }
}

// ======================= TF32 tensor-core GEMM ==============================
// C[M,N] = act(A[M,K] @ B[K,N] + bias)
// CTA 128x128xBK32, 8 warps (2x4), warp tile 64x32, mma m16n8k8 tf32.
// Double-buffered dynamic smem, 1 sync per chunk.
// As: swizzled [row][k^((row&7)<<2)], stride 32 (conflict-free LDS + STS.128)
// Bs: [k][n] stride 136.
// MODE 0: store; MODE 1: exact gelu; MODE 2: C += v

#define BM 128
#define BN 128
#define BKG 32
#define ASTG (BM*BKG)        // 4096 u32 per stage
#define BS_LD 136
#define BSTG (BKG*BS_LD)     // 4352 u32 per stage
#define GEMM_SMEM_BYTES ((2*ASTG + 2*BSTG)*4)   // 67584

template <int MODE>
__device__ __forceinline__ void tf32_gemm_core(
    const float* __restrict__ A, const float* __restrict__ B,
    const float* __restrict__ bias, float* __restrict__ C,
    int N, int K)
{
    extern __shared__ unsigned smemU[];
    unsigned* As = smemU;             // [2][ASTG]
    unsigned* Bs = smemU + 2 * ASTG;  // [2][BSTG]

    const int tid  = threadIdx.x;
    const int lane = tid & 31;
    const int wid  = tid >> 5;
    const int wm   = wid >> 2;            // 0..1
    const int wn   = wid & 3;             // 0..3
    const int rowBase = blockIdx.y * BM;
    const int colBase = blockIdx.x * BN;
    const int lq = lane >> 2;   // 0..7
    const int lr = lane & 3;    // 0..3

    float4 aPre[4], bPre[4];

    auto loadA = [&](int k0) {
#pragma unroll
        for (int i = 0; i < 4; i++) {
            int fi = tid + i * 256;            // 1024 float4 = 128x32
            int r = fi >> 3, c4 = fi & 7;
            aPre[i] = *(const float4*)(A + (size_t)(rowBase + r) * K + k0 + c4 * 4);
        }
    };
    auto loadB = [&](int k0) {
#pragma unroll
        for (int i = 0; i < 4; i++) {
            int fi = tid + i * 256;            // 1024 float4 = 32x128
            int r = fi >> 5, c4 = fi & 31;
            bPre[i] = *(const float4*)(B + (size_t)(k0 + r) * N + colBase + c4 * 4);
        }
    };
    auto storeAB = [&](int st) {
#pragma unroll
        for (int i = 0; i < 4; i++) {
            int fi = tid + i * 256;
            int r = fi >> 3, c4 = fi & 7;
            unsigned* d = As + st * ASTG + r * BKG + ((c4 * 4) ^ ((r & 7) << 2));
            d[0] = f2tf32(aPre[i].x); d[1] = f2tf32(aPre[i].y);
            d[2] = f2tf32(aPre[i].z); d[3] = f2tf32(aPre[i].w);
        }
#pragma unroll
        for (int i = 0; i < 4; i++) {
            int fi = tid + i * 256;
            int r = fi >> 5, c4 = fi & 31;
            unsigned* d = Bs + st * BSTG + r * BS_LD + c4 * 4;
            d[0] = f2tf32(bPre[i].x); d[1] = f2tf32(bPre[i].y);
            d[2] = f2tf32(bPre[i].z); d[3] = f2tf32(bPre[i].w);
        }
    };

    float acc[4][4][4];
#pragma unroll
    for (int i = 0; i < 4; i++)
#pragma unroll
        for (int j = 0; j < 4; j++)
#pragma unroll
            for (int t = 0; t < 4; t++) acc[i][j][t] = 0.f;

    loadA(0); loadB(0);
    storeAB(0);
    __syncthreads();

    int st = 0;
    for (int k0 = 0; k0 < K; k0 += BKG) {
        const bool last = (k0 + BKG >= K);
        if (!last) { loadA(k0 + BKG); loadB(k0 + BKG); }

        const unsigned* Ab = As + st * ASTG;
        const unsigned* Bb = Bs + st * BSTG;
#pragma unroll
        for (int s = 0; s < 4; s++) {
            const int kc = s * 8 + lr;
            const int sw0 = kc ^ (lq << 2);
            const int sw1 = (kc + 4) ^ (lq << 2);
            unsigned af[4][4];
#pragma unroll
            for (int mt = 0; mt < 4; mt++) {
                int r0 = wm * 64 + mt * 16 + lq;
                af[mt][0] = Ab[r0 * BKG + sw0];
                af[mt][1] = Ab[(r0 + 8) * BKG + sw0];
                af[mt][2] = Ab[r0 * BKG + sw1];
                af[mt][3] = Ab[(r0 + 8) * BKG + sw1];
            }
            unsigned bf[4][2];
#pragma unroll
            for (int nt = 0; nt < 4; nt++) {
                int c = wn * 32 + nt * 8 + lq;
                bf[nt][0] = Bb[kc * BS_LD + c];
                bf[nt][1] = Bb[(kc + 4) * BS_LD + c];
            }
#pragma unroll
            for (int mt = 0; mt < 4; mt++)
#pragma unroll
                for (int nt = 0; nt < 4; nt++) {
                    asm volatile(
                        "mma.sync.aligned.m16n8k8.row.col.f32.tf32.tf32.f32 "
                        "{%0,%1,%2,%3}, {%4,%5,%6,%7}, {%8,%9}, {%0,%1,%2,%3};"
                        : "+f"(acc[mt][nt][0]), "+f"(acc[mt][nt][1]),
                          "+f"(acc[mt][nt][2]), "+f"(acc[mt][nt][3])
                        : "r"(af[mt][0]), "r"(af[mt][1]),
                          "r"(af[mt][2]), "r"(af[mt][3]),
                          "r"(bf[nt][0]), "r"(bf[nt][1]));
                }
        }

        if (!last) {
            storeAB(st ^ 1);
            __syncthreads();
            st ^= 1;
        }
    }

    // epilogue
#pragma unroll
    for (int mt = 0; mt < 4; mt++) {
        int row = rowBase + wm * 64 + mt * 16 + lq;
#pragma unroll
        for (int nt = 0; nt < 4; nt++) {
            int col = colBase + wn * 32 + nt * 8 + lr * 2;
            float b0 = bias[col], b1 = bias[col + 1];
            float v00 = acc[mt][nt][0] + b0;
            float v01 = acc[mt][nt][1] + b1;
            float v10 = acc[mt][nt][2] + b0;
            float v11 = acc[mt][nt][3] + b1;
            if (MODE == 1) {
                v00 = 0.5f * v00 * (1.0f + erff(v00 * 0.70710678118654752f));
                v01 = 0.5f * v01 * (1.0f + erff(v01 * 0.70710678118654752f));
                v10 = 0.5f * v10 * (1.0f + erff(v10 * 0.70710678118654752f));
                v11 = 0.5f * v11 * (1.0f + erff(v11 * 0.70710678118654752f));
            }
            float* C0 = C + (size_t)row * N + col;
            float* C1 = C + (size_t)(row + 8) * N + col;
            if (MODE == 2) {
                C0[0] += v00; C0[1] += v01;
                C1[0] += v10; C1[1] += v11;
            } else {
                C0[0] = v00; C0[1] = v01;
                C1[0] = v10; C1[1] = v11;
            }
        }
    }
}

template <int MODE>
__global__ __launch_bounds__(256) void tf32_gemm_kernel(
    const float* __restrict__ A, const float* __restrict__ B,
    const float* __restrict__ bias, float* __restrict__ C,
    int N, int K)
{
    tf32_gemm_core<MODE>(A, B, bias, C, N, K);
}

__global__ __launch_bounds__(256) void tf32_gemm_qkv_kernel(
    const float* __restrict__ A,
    const float* __restrict__ Wq, const float* __restrict__ Wk, const float* __restrict__ Wv,
    const float* __restrict__ bq, const float* __restrict__ bk, const float* __restrict__ bv,
    float* __restrict__ q, float* __restrict__ k, float* __restrict__ v)
{
    const float* B; const float* bias; float* C;
    if (blockIdx.z == 0)      { B = Wq; bias = bq; C = q; }
    else if (blockIdx.z == 1) { B = Wk; bias = bk; C = k; }
    else                      { B = Wv; bias = bv; C = v; }
    tf32_gemm_core<0>(A, B, bias, C, DMODEL, DMODEL);
}

// ======================= TF32 tensor-core attention =========================
// CTA: 64 q-rows x full 512 keys. 8 warps as 4(row)x2(col); warp tile 16x32.
// QK^T and P@V via m16n8k8 tf32; exact softmax in fp32 smem.
#define AQ_LD 68
#define AS_LDS 516
#define ATTN_SMEM_WORDS (2 * 64 * AQ_LD + 64 * AS_LDS)
#define ATTN_SMEM_BYTES (ATTN_SMEM_WORDS * 4)      // 166912

__global__ __launch_bounds__(256) void attn_kernel(
    const float* __restrict__ q, const float* __restrict__ k,
    const float* __restrict__ v, float* __restrict__ x)
{
    extern __shared__ unsigned smA[];
    unsigned* Qs  = smA;                    // [64][68] tf32
    unsigned* KVs = smA + 64 * AQ_LD;       // [64][68] tf32 (K then V tiles)
    float*    S   = (float*)(smA + 2 * 64 * AQ_LD);   // [64][516] fp32

    const int tid = threadIdx.x;
    const int lane = tid & 31;
    const int wid = tid >> 5;
    const int wm = wid >> 1;                // 0..3 (rows)
    const int wn = wid & 1;                 // 0..1 (cols)
    const int lq = lane >> 2;
    const int lr = lane & 3;

    const int qt = blockIdx.x;
    const int bh = blockIdx.y;
    const int b = bh / NHEAD, h = bh % NHEAD;

    const float* qb = q + ((size_t)b * SEQ + qt * 64) * DMODEL + h * HDIM;
    const float* kb = k + (size_t)b * SEQ * DMODEL + h * HDIM;
    const float* vb = v + (size_t)b * SEQ * DMODEL + h * HDIM;

    // load Q tile (64x64) -> tf32 smem
#pragma unroll
    for (int c = 0; c < 4; c++) {
        int fi = tid + c * 256;
        int row = fi >> 4, col4 = fi & 15;
        float4 t = *(const float4*)(qb + (size_t)row * DMODEL + col4 * 4);
        unsigned* d = Qs + row * AQ_LD + col4 * 4;
        d[0] = f2tf32(t.x); d[1] = f2tf32(t.y);
        d[2] = f2tf32(t.z); d[3] = f2tf32(t.w);
    }

    // --- S = (Q @ K^T) / 8 ---
    for (int kt = 0; kt < 8; kt++) {
        __syncthreads();
#pragma unroll
        for (int c = 0; c < 4; c++) {
            int fi = tid + c * 256;
            int row = fi >> 4, col4 = fi & 15;
            float4 t = *(const float4*)(kb + (size_t)(kt * 64 + row) * DMODEL + col4 * 4);
            unsigned* d = KVs + row * AQ_LD + col4 * 4;
            d[0] = f2tf32(t.x); d[1] = f2tf32(t.y);
            d[2] = f2tf32(t.z); d[3] = f2tf32(t.w);
        }
        __syncthreads();

        float acc[4][4];
#pragma unroll
        for (int nt = 0; nt < 4; nt++)
#pragma unroll
            for (int t = 0; t < 4; t++) acc[nt][t] = 0.f;

        const int r0 = wm * 16 + lq;
#pragma unroll
        for (int s = 0; s < 8; s++) {
            const int kc = s * 8 + lr;
            unsigned a0 = Qs[r0 * AQ_LD + kc];
            unsigned a1 = Qs[(r0 + 8) * AQ_LD + kc];
            unsigned a2 = Qs[r0 * AQ_LD + kc + 4];
            unsigned a3 = Qs[(r0 + 8) * AQ_LD + kc + 4];
#pragma unroll
            for (int nt = 0; nt < 4; nt++) {
                int c = wn * 32 + nt * 8 + lq;
                unsigned b0 = KVs[c * AQ_LD + kc];
                unsigned b1 = KVs[c * AQ_LD + kc + 4];
                asm volatile(
                    "mma.sync.aligned.m16n8k8.row.col.f32.tf32.tf32.f32 "
                    "{%0,%1,%2,%3}, {%4,%5,%6,%7}, {%8,%9}, {%0,%1,%2,%3};"
                    : "+f"(acc[nt][0]), "+f"(acc[nt][1]),
                      "+f"(acc[nt][2]), "+f"(acc[nt][3])
                    : "r"(a0), "r"(a1), "r"(a2), "r"(a3),
                      "r"(b0), "r"(b1));
            }
        }
#pragma unroll
        for (int nt = 0; nt < 4; nt++) {
            int col = kt * 64 + wn * 32 + nt * 8 + lr * 2;
            S[r0 * AS_LDS + col]           = acc[nt][0] * 0.125f;
            S[r0 * AS_LDS + col + 1]       = acc[nt][1] * 0.125f;
            S[(r0 + 8) * AS_LDS + col]     = acc[nt][2] * 0.125f;
            S[(r0 + 8) * AS_LDS + col + 1] = acc[nt][3] * 0.125f;
        }
    }
    __syncthreads();

    // --- softmax rows (warp per row, 8 rows per warp) ---
    for (int rr = 0; rr < 8; rr++) {
        float* Sr = S + (wid * 8 + rr) * AS_LDS;
        float m = -1e30f;
        for (int j = lane; j < SEQ; j += 32) m = fmaxf(m, Sr[j]);
#pragma unroll
        for (int o = 16; o > 0; o >>= 1) m = fmaxf(m, __shfl_xor_sync(0xffffffffu, m, o));
        float s = 0.f;
        for (int j = lane; j < SEQ; j += 32) {
            float e = __expf(Sr[j] - m);
            Sr[j] = e;
            s += e;
        }
#pragma unroll
        for (int o = 16; o > 0; o >>= 1) s += __shfl_xor_sync(0xffffffffu, s, o);
        float inv = 1.f / s;
        for (int j = lane; j < SEQ; j += 32) Sr[j] *= inv;
    }

    // --- O = P @ V ---
    float o[4][4];
#pragma unroll
    for (int nt = 0; nt < 4; nt++)
#pragma unroll
        for (int t = 0; t < 4; t++) o[nt][t] = 0.f;

    const int r0 = wm * 16 + lq;
    for (int kt = 0; kt < 8; kt++) {
        __syncthreads();
#pragma unroll
        for (int c = 0; c < 4; c++) {
            int fi = tid + c * 256;
            int row = fi >> 4, col4 = fi & 15;
            float4 t = *(const float4*)(vb + (size_t)(kt * 64 + row) * DMODEL + col4 * 4);
            unsigned* d = KVs + row * AQ_LD + col4 * 4;
            d[0] = f2tf32(t.x); d[1] = f2tf32(t.y);
            d[2] = f2tf32(t.z); d[3] = f2tf32(t.w);
        }
        __syncthreads();

#pragma unroll
        for (int s = 0; s < 8; s++) {
            const int kc = s * 8 + lr;
            unsigned a0 = f2tf32(S[r0 * AS_LDS + kt * 64 + kc]);
            unsigned a1 = f2tf32(S[(r0 + 8) * AS_LDS + kt * 64 + kc]);
            unsigned a2 = f2tf32(S[r0 * AS_LDS + kt * 64 + kc + 4]);
            unsigned a3 = f2tf32(S[(r0 + 8) * AS_LDS + kt * 64 + kc + 4]);
#pragma unroll
            for (int nt = 0; nt < 4; nt++) {
                int c = wn * 32 + nt * 8 + lq;
                unsigned b0 = KVs[kc * AQ_LD + c];
                unsigned b1 = KVs[(kc + 4) * AQ_LD + c];
                asm volatile(
                    "mma.sync.aligned.m16n8k8.row.col.f32.tf32.tf32.f32 "
                    "{%0,%1,%2,%3}, {%4,%5,%6,%7}, {%8,%9}, {%0,%1,%2,%3};"
                    : "+f"(o[nt][0]), "+f"(o[nt][1]),
                      "+f"(o[nt][2]), "+f"(o[nt][3])
                    : "r"(a0), "r"(a1), "r"(a2), "r"(a3),
                      "r"(b0), "r"(b1));
            }
        }
    }

    // residual add into x (unique writer per element)
    float* xb = x + ((size_t)b * SEQ + qt * 64) * DMODEL + h * HDIM;
#pragma unroll
    for (int nt = 0; nt < 4; nt++) {
        int col = wn * 32 + nt * 8 + lr * 2;
        xb[(size_t)r0 * DMODEL + col]           += o[nt][0];
        xb[(size_t)r0 * DMODEL + col + 1]       += o[nt][1];
        xb[(size_t)(r0 + 8) * DMODEL + col]     += o[nt][2];
        xb[(size_t)(r0 + 8) * DMODEL + col + 1] += o[nt][3];
    }
}

// ---------------- launch ----------------------------------------------------
extern "C" void kernel_launch(void* const* d_in, const int* in_sizes, int n_in,
                              void* d_out, int out_size)
{
    const float* x_in = (const float*)d_in[0];
    const float* Wq = (const float*)d_in[1];
    const float* bq = (const float*)d_in[2];
    const float* Wk = (const float*)d_in[3];
    const float* bk = (const float*)d_in[4];
    const float* Wv = (const float*)d_in[5];
    const float* bv = (const float*)d_in[6];
    const float* g1 = (const float*)d_in[7];
    const float* be1 = (const float*)d_in[8];
    const float* g2 = (const float*)d_in[9];
    const float* be2 = (const float*)d_in[10];
    const float* W0 = (const float*)d_in[11];
    const float* b0 = (const float*)d_in[12];
    const float* W1 = (const float*)d_in[13];
    const float* b1 = (const float*)d_in[14];

    float* x = (float*)d_out;

    void *p_xln, *p_q, *p_k, *p_v, *p_h1;
    cudaGetSymbolAddress(&p_xln, g_xln);
    cudaGetSymbolAddress(&p_q, g_q);
    cudaGetSymbolAddress(&p_k, g_k);
    cudaGetSymbolAddress(&p_v, g_v);
    cudaGetSymbolAddress(&p_h1, g_h1);
    float* xln = (float*)p_xln;
    float* q = (float*)p_q;
    float* k = (float*)p_k;
    float* v = (float*)p_v;
    float* h1 = (float*)p_h1;

    cudaFuncSetAttribute(attn_kernel, cudaFuncAttributeMaxDynamicSharedMemorySize,
                         ATTN_SMEM_BYTES);
    cudaFuncSetAttribute(tf32_gemm_qkv_kernel, cudaFuncAttributeMaxDynamicSharedMemorySize,
                         GEMM_SMEM_BYTES);
    cudaFuncSetAttribute(tf32_gemm_kernel<1>, cudaFuncAttributeMaxDynamicSharedMemorySize,
                         GEMM_SMEM_BYTES);
    cudaFuncSetAttribute(tf32_gemm_kernel<2>, cudaFuncAttributeMaxDynamicSharedMemorySize,
                         GEMM_SMEM_BYTES);

    cudaMemcpyAsync(x, x_in, (size_t)NTOK * DMODEL * sizeof(float),
                    cudaMemcpyDeviceToDevice, 0);

    const dim3 gemmQKV(DMODEL / BN, NTOK / BM, 3);  // (6,16,3)
    const dim3 gemmFF1(FFDIM / BN, NTOK / BM);      // (24,16)
    const dim3 gemmFF2(DMODEL / BN, NTOK / BM);     // (6,16)
    const dim3 attnGrid(SEQ / 64, BATCH * NHEAD);   // (8,48)

    for (int blk = 0; blk < NBLOCKS; blk++) {
        ln_kernel<<<NTOK, 256>>>(x, g1, be1, xln);
        tf32_gemm_qkv_kernel<<<gemmQKV, 256, GEMM_SMEM_BYTES>>>(
            xln, Wq, Wk, Wv, bq, bk, bv, q, k, v);
        attn_kernel<<<attnGrid, 256, ATTN_SMEM_BYTES>>>(q, k, v, x);
        ln_kernel<<<NTOK, 256>>>(x, g2, be2, xln);
        tf32_gemm_kernel<1><<<gemmFF1, 256, GEMM_SMEM_BYTES>>>(xln, W0, b0, h1, FFDIM, DMODEL);
        tf32_gemm_kernel<2><<<gemmFF2, 256, GEMM_SMEM_BYTES>>>(h1, W1, b1, x, DMODEL, FFDIM);
    }
}

// round 5
// speedup vs baseline: 3.9469x; 1.1823x over previous
#include <cuda_runtime.h>
#include <cuda_bf16.h>
#include <math.h>

// Problem constants
#define BATCH 4
#define SEQ   512
#define DMODEL 768
#define FFDIM 3072
#define NHEAD 12
#define HDIM  64
#define NTOK  (BATCH*SEQ)          // 2048
#define NBLOCKS 12

// ---------------- scratch (device globals; no allocation allowed) -----------
__device__ float g_xln[NTOK * DMODEL];
__device__ float g_q  [NTOK * DMODEL];
__device__ float g_k  [NTOK * DMODEL];
__device__ float g_v  [NTOK * DMODEL];
__device__ float g_h1 [NTOK * FFDIM];
// tf32-rounded weights
__device__ float g_wq[DMODEL * DMODEL];
__device__ float g_wk[DMODEL * DMODEL];
__device__ float g_wv[DMODEL * DMODEL];
__device__ float g_w0[DMODEL * FFDIM];
__device__ float g_w1[FFDIM * DMODEL];

__device__ __forceinline__ unsigned f2tf32(float f) {
    unsigned r;
    asm("cvt.rna.tf32.f32 %0, %1;" : "=r"(r) : "f"(f));
    return r;
}
__device__ __forceinline__ float f2tf32f(float f) {
    return __uint_as_float(f2tf32(f));
}
__device__ __forceinline__ void cpa16(unsigned dst, const void* src) {
    asm volatile("cp.async.cg.shared.global [%0], [%1], 16;\n" :: "r"(dst), "l"(src));
}
__device__ __forceinline__ void cpa_commit() {
    asm volatile("cp.async.commit_group;\n" ::: "memory");
}
template <int N>
__device__ __forceinline__ void cpa_wait() {
    asm volatile("cp.async.wait_group %0;\n" :: "n"(N) : "memory");
}
__device__ __forceinline__ unsigned smem_u32(const void* p) {
    unsigned r;
    asm("{ .reg .u64 t; cvta.to.shared.u64 t, %1; cvt.u32.u64 %0, t; }"
        : "=r"(r) : "l"(p));
    return r;
}

// ---------------- weight tf32 pre-round kernel ------------------------------
__global__ __launch_bounds__(256) void cvt_kernel(
    const float* __restrict__ src, float* __restrict__ dst, int n4)
{
    int i = blockIdx.x * 256 + threadIdx.x;
    if (i < n4) {
        float4 v = *(const float4*)(src + (size_t)i * 4);
        v.x = f2tf32f(v.x); v.y = f2tf32f(v.y);
        v.z = f2tf32f(v.z); v.w = f2tf32f(v.w);
        *(float4*)(dst + (size_t)i * 4) = v;
    }
}

// ---------------- LayerNorm: one block per row; outputs tf32-rounded --------
__global__ __launch_bounds__(256) void ln_kernel(
    const float* __restrict__ x, const float* __restrict__ g,
    const float* __restrict__ be, float* __restrict__ y)
{
    __shared__ float redS[8];
    __shared__ float redS2[8];
    const int r = blockIdx.x;
    const int tid = threadIdx.x;
    const float* xr = x + (size_t)r * DMODEL;

    float vals[3];
    float s = 0.f, s2 = 0.f;
#pragma unroll
    for (int c = 0; c < 3; c++) {
        float v = xr[tid + c * 256];
        vals[c] = v;
        s += v; s2 += v * v;
    }
#pragma unroll
    for (int o = 16; o > 0; o >>= 1) {
        s  += __shfl_xor_sync(0xffffffffu, s,  o);
        s2 += __shfl_xor_sync(0xffffffffu, s2, o);
    }
    const int wid = tid >> 5, lane = tid & 31;
    if (lane == 0) { redS[wid] = s; redS2[wid] = s2; }
    __syncthreads();
    if (tid < 32) {
        float a  = (tid < 8) ? redS [tid] : 0.f;
        float a2 = (tid < 8) ? redS2[tid] : 0.f;
#pragma unroll
        for (int o = 4; o > 0; o >>= 1) {
            a  += __shfl_xor_sync(0xffffffffu, a,  o);
            a2 += __shfl_xor_sync(0xffffffffu, a2, o);
        }
        if (tid == 0) { redS[0] = a; redS2[0] = a2; }
    }
    __syncthreads();
    const float mu  = redS[0]  * (1.f / DMODEL);
    const float var = redS2[0] * (1.f / DMODEL) - mu * mu;
    const float inv = rsqrtf(var + 1e-5f);
    float* yr = y + (size_t)r * DMODEL;
#pragma unroll
    for (int c = 0; c < 3; c++) {
        int j = tid + c * 256;
        yr[j] = f2tf32f((vals[c] - mu) * inv * g[j] + be[j]);
    }
}

// ======================= TF32 tensor-core GEMM ==============================
// C[M,N] = act(A[M,K] @ B[K,N] + bias).  Inputs pre-rounded to tf32.
// CTA tile (MT*32)x128xBK32; 8 warps as 2x4; warp tile (MT*16)x32.
// 3-stage cp.async pipeline, 1 sync per chunk.
// As swizzled [row][k^((row&7)<<2)] stride 32; Bs [k][n] stride 136.
// MODE 0: store; MODE 1: gelu + tf32-round store; MODE 2: C += v;
// MODE 3: tf32-round store

#define BN 128
#define BKG 32
#define BS_LD 136
#define BSTG (BKG*BS_LD)     // 4352 u32 per stage
#define NSTAGE 3

template <int MT, int MODE>
__device__ __forceinline__ void tf32_gemm_core(
    const float* __restrict__ A, const float* __restrict__ B,
    const float* __restrict__ bias, float* __restrict__ C,
    int N, int K)
{
    constexpr int BMv  = MT * 32;          // 128 or 64
    constexpr int ASTG = BMv * BKG;        // u32 per A stage
    constexpr int AIT  = (BMv * BKG) / 1024;  // float4 loads per thread (4 or 2)

    extern __shared__ unsigned smemU[];
    unsigned* As = smemU;                    // [NSTAGE][ASTG]
    unsigned* Bs = smemU + NSTAGE * ASTG;    // [NSTAGE][BSTG]
    const unsigned asBase = smem_u32(As);
    const unsigned bsBase = smem_u32(Bs);

    const int tid  = threadIdx.x;
    const int lane = tid & 31;
    const int wid  = tid >> 5;
    const int wm   = wid >> 2;            // 0..1
    const int wn   = wid & 3;             // 0..3
    const int rowBase = blockIdx.y * BMv;
    const int colBase = blockIdx.x * BN;
    const int lq = lane >> 2;   // 0..7
    const int lr = lane & 3;    // 0..3

    auto issue = [&](int k0, int st) {
#pragma unroll
        for (int i = 0; i < AIT; i++) {
            int fi = tid + i * 256;
            int r = fi >> 3, c4 = fi & 7;
            unsigned dst = asBase + (st * ASTG + r * BKG + ((c4 * 4) ^ ((r & 7) << 2))) * 4u;
            cpa16(dst, A + (size_t)(rowBase + r) * K + k0 + c4 * 4);
        }
#pragma unroll
        for (int i = 0; i < 4; i++) {
            int fi = tid + i * 256;
            int r = fi >> 5, c4 = fi & 31;
            unsigned dst = bsBase + (st * BSTG + r * BS_LD + c4 * 4) * 4u;
            cpa16(dst, B + (size_t)(k0 + r) * N + colBase + c4 * 4);
        }
    };

    float acc[MT][4][4];
#pragma unroll
    for (int i = 0; i < MT; i++)
#pragma unroll
        for (int j = 0; j < 4; j++)
#pragma unroll
            for (int t = 0; t < 4; t++) acc[i][j][t] = 0.f;

    const int nch = K / BKG;
    issue(0, 0); cpa_commit();
    issue(BKG, 1); cpa_commit();

    for (int c = 0; c < nch; c++) {
        cpa_wait<1>();
        __syncthreads();

        const int nc = c + 2;
        if (nc < nch) issue(nc * BKG, nc % NSTAGE);
        cpa_commit();

        const unsigned* Ab = As + (c % NSTAGE) * ASTG;
        const unsigned* Bb = Bs + (c % NSTAGE) * BSTG;
#pragma unroll
        for (int s = 0; s < 4; s++) {
            const int kc = s * 8 + lr;
            const int sw0 = kc ^ (lq << 2);
            const int sw1 = (kc + 4) ^ (lq << 2);
            unsigned af[MT][4];
#pragma unroll
            for (int mt = 0; mt < MT; mt++) {
                int r0 = wm * (MT * 16) + mt * 16 + lq;
                af[mt][0] = Ab[r0 * BKG + sw0];
                af[mt][1] = Ab[(r0 + 8) * BKG + sw0];
                af[mt][2] = Ab[r0 * BKG + sw1];
                af[mt][3] = Ab[(r0 + 8) * BKG + sw1];
            }
            unsigned bf[4][2];
#pragma unroll
            for (int nt = 0; nt < 4; nt++) {
                int cc = wn * 32 + nt * 8 + lq;
                bf[nt][0] = Bb[kc * BS_LD + cc];
                bf[nt][1] = Bb[(kc + 4) * BS_LD + cc];
            }
#pragma unroll
            for (int mt = 0; mt < MT; mt++)
#pragma unroll
                for (int nt = 0; nt < 4; nt++) {
                    asm volatile(
                        "mma.sync.aligned.m16n8k8.row.col.f32.tf32.tf32.f32 "
                        "{%0,%1,%2,%3}, {%4,%5,%6,%7}, {%8,%9}, {%0,%1,%2,%3};"
                        : "+f"(acc[mt][nt][0]), "+f"(acc[mt][nt][1]),
                          "+f"(acc[mt][nt][2]), "+f"(acc[mt][nt][3])
                        : "r"(af[mt][0]), "r"(af[mt][1]),
                          "r"(af[mt][2]), "r"(af[mt][3]),
                          "r"(bf[nt][0]), "r"(bf[nt][1]));
                }
        }
        __syncthreads();
    }

    // epilogue
#pragma unroll
    for (int mt = 0; mt < MT; mt++) {
        int row = rowBase + wm * (MT * 16) + mt * 16 + lq;
#pragma unroll
        for (int nt = 0; nt < 4; nt++) {
            int col = colBase + wn * 32 + nt * 8 + lr * 2;
            float b0 = bias[col], b1 = bias[col + 1];
            float v00 = acc[mt][nt][0] + b0;
            float v01 = acc[mt][nt][1] + b1;
            float v10 = acc[mt][nt][2] + b0;
            float v11 = acc[mt][nt][3] + b1;
            if (MODE == 1) {
                v00 = f2tf32f(0.5f * v00 * (1.0f + erff(v00 * 0.70710678118654752f)));
                v01 = f2tf32f(0.5f * v01 * (1.0f + erff(v01 * 0.70710678118654752f)));
                v10 = f2tf32f(0.5f * v10 * (1.0f + erff(v10 * 0.70710678118654752f)));
                v11 = f2tf32f(0.5f * v11 * (1.0f + erff(v11 * 0.70710678118654752f)));
            }
            if (MODE == 3) {
                v00 = f2tf32f(v00); v01 = f2tf32f(v01);
                v10 = f2tf32f(v10); v11 = f2tf32f(v11);
            }
            float* C0 = C + (size_t)row * N + col;
            float* C1 = C + (size_t)(row + 8) * N + col;
            if (MODE == 2) {
                C0[0] += v00; C0[1] += v01;
                C1[0] += v10; C1[1] += v11;
            } else {
                C0[0] = v00; C0[1] = v01;
                C1[0] = v10; C1[1] = v11;
            }
        }
    }
}

template <int MT, int MODE>
__global__ __launch_bounds__(256) void tf32_gemm_kernel(
    const float* __restrict__ A, const float* __restrict__ B,
    const float* __restrict__ bias, float* __restrict__ C,
    int N, int K)
{
    tf32_gemm_core<MT, MODE>(A, B, bias, C, N, K);
}

__global__ __launch_bounds__(256) void tf32_gemm_qkv_kernel(
    const float* __restrict__ A,
    const float* __restrict__ Wq, const float* __restrict__ Wk, const float* __restrict__ Wv,
    const float* __restrict__ bq, const float* __restrict__ bk, const float* __restrict__ bv,
    float* __restrict__ q, float* __restrict__ k, float* __restrict__ v)
{
    const float* B; const float* bias; float* C;
    if (blockIdx.z == 0)      { B = Wq; bias = bq; C = q; }
    else if (blockIdx.z == 1) { B = Wk; bias = bk; C = k; }
    else                      { B = Wv; bias = bv; C = v; }
    tf32_gemm_core<4, 3>(A, B, bias, C, DMODEL, DMODEL);
}

#define GEMM128_SMEM ((NSTAGE * (128*BKG) + NSTAGE * BSTG) * 4)   // 101376
#define GEMM64_SMEM  ((NSTAGE * (64*BKG)  + NSTAGE * BSTG) * 4)   // 76800

// ======================= TF32 tensor-core attention =========================
// CTA: 64 q-rows x full 512 keys. 8 warps as 4(row)x2(col); warp tile 16x32.
// Inputs q/k/v are tf32-pre-rounded -> smem fills are raw copies.
#define AQ_LD 68
#define AS_LDS 516
#define ATTN_SMEM_WORDS (2 * 64 * AQ_LD + 64 * AS_LDS)
#define ATTN_SMEM_BYTES (ATTN_SMEM_WORDS * 4)      // 166912

__global__ __launch_bounds__(256) void attn_kernel(
    const float* __restrict__ q, const float* __restrict__ k,
    const float* __restrict__ v, float* __restrict__ x)
{
    extern __shared__ unsigned smA[];
    unsigned* Qs  = smA;                    // [64][68]
    unsigned* KVs = smA + 64 * AQ_LD;       // [64][68]
    float*    S   = (float*)(smA + 2 * 64 * AQ_LD);   // [64][516]

    const int tid = threadIdx.x;
    const int lane = tid & 31;
    const int wid = tid >> 5;
    const int wm = wid >> 1;                // 0..3
    const int wn = wid & 1;                 // 0..1
    const int lq = lane >> 2;
    const int lr = lane & 3;

    const int qt = blockIdx.x;
    const int bh = blockIdx.y;
    const int b = bh / NHEAD, h = bh % NHEAD;

    const float* qb = q + ((size_t)b * SEQ + qt * 64) * DMODEL + h * HDIM;
    const float* kb = k + (size_t)b * SEQ * DMODEL + h * HDIM;
    const float* vb = v + (size_t)b * SEQ * DMODEL + h * HDIM;

#pragma unroll
    for (int c = 0; c < 4; c++) {
        int fi = tid + c * 256;
        int row = fi >> 4, col4 = fi & 15;
        float4 t = *(const float4*)(qb + (size_t)row * DMODEL + col4 * 4);
        unsigned* d = Qs + row * AQ_LD + col4 * 4;
        d[0] = __float_as_uint(t.x); d[1] = __float_as_uint(t.y);
        d[2] = __float_as_uint(t.z); d[3] = __float_as_uint(t.w);
    }

    // --- S = (Q @ K^T) / 8 ---
    for (int kt = 0; kt < 8; kt++) {
        __syncthreads();
#pragma unroll
        for (int c = 0; c < 4; c++) {
            int fi = tid + c * 256;
            int row = fi >> 4, col4 = fi & 15;
            float4 t = *(const float4*)(kb + (size_t)(kt * 64 + row) * DMODEL + col4 * 4);
            unsigned* d = KVs + row * AQ_LD + col4 * 4;
            d[0] = __float_as_uint(t.x); d[1] = __float_as_uint(t.y);
            d[2] = __float_as_uint(t.z); d[3] = __float_as_uint(t.w);
        }
        __syncthreads();

        float acc[4][4];
#pragma unroll
        for (int nt = 0; nt < 4; nt++)
#pragma unroll
            for (int t = 0; t < 4; t++) acc[nt][t] = 0.f;

        const int r0 = wm * 16 + lq;
#pragma unroll
        for (int s = 0; s < 8; s++) {
            const int kc = s * 8 + lr;
            unsigned a0 = Qs[r0 * AQ_LD + kc];
            unsigned a1 = Qs[(r0 + 8) * AQ_LD + kc];
            unsigned a2 = Qs[r0 * AQ_LD + kc + 4];
            unsigned a3 = Qs[(r0 + 8) * AQ_LD + kc + 4];
#pragma unroll
            for (int nt = 0; nt < 4; nt++) {
                int c = wn * 32 + nt * 8 + lq;
                unsigned b0 = KVs[c * AQ_LD + kc];
                unsigned b1 = KVs[c * AQ_LD + kc + 4];
                asm volatile(
                    "mma.sync.aligned.m16n8k8.row.col.f32.tf32.tf32.f32 "
                    "{%0,%1,%2,%3}, {%4,%5,%6,%7}, {%8,%9}, {%0,%1,%2,%3};"
                    : "+f"(acc[nt][0]), "+f"(acc[nt][1]),
                      "+f"(acc[nt][2]), "+f"(acc[nt][3])
                    : "r"(a0), "r"(a1), "r"(a2), "r"(a3),
                      "r"(b0), "r"(b1));
            }
        }
#pragma unroll
        for (int nt = 0; nt < 4; nt++) {
            int col = kt * 64 + wn * 32 + nt * 8 + lr * 2;
            S[r0 * AS_LDS + col]           = acc[nt][0] * 0.125f;
            S[r0 * AS_LDS + col + 1]       = acc[nt][1] * 0.125f;
            S[(r0 + 8) * AS_LDS + col]     = acc[nt][2] * 0.125f;
            S[(r0 + 8) * AS_LDS + col + 1] = acc[nt][3] * 0.125f;
        }
    }
    __syncthreads();

    // --- softmax rows ---
    for (int rr = 0; rr < 8; rr++) {
        float* Sr = S + (wid * 8 + rr) * AS_LDS;
        float m = -1e30f;
        for (int j = lane; j < SEQ; j += 32) m = fmaxf(m, Sr[j]);
#pragma unroll
        for (int o = 16; o > 0; o >>= 1) m = fmaxf(m, __shfl_xor_sync(0xffffffffu, m, o));
        float s = 0.f;
        for (int j = lane; j < SEQ; j += 32) {
            float e = __expf(Sr[j] - m);
            Sr[j] = e;
            s += e;
        }
#pragma unroll
        for (int o = 16; o > 0; o >>= 1) s += __shfl_xor_sync(0xffffffffu, s, o);
        float inv = 1.f / s;
        for (int j = lane; j < SEQ; j += 32) Sr[j] *= inv;
    }

    // --- O = P @ V ---
    float o[4][4];
#pragma unroll
    for (int nt = 0; nt < 4; nt++)
#pragma unroll
        for (int t = 0; t < 4; t++) o[nt][t] = 0.f;

    const int r0 = wm * 16 + lq;
    for (int kt = 0; kt < 8; kt++) {
        __syncthreads();
#pragma unroll
        for (int c = 0; c < 4; c++) {
            int fi = tid + c * 256;
            int row = fi >> 4, col4 = fi & 15;
            float4 t = *(const float4*)(vb + (size_t)(kt * 64 + row) * DMODEL + col4 * 4);
            unsigned* d = KVs + row * AQ_LD + col4 * 4;
            d[0] = __float_as_uint(t.x); d[1] = __float_as_uint(t.y);
            d[2] = __float_as_uint(t.z); d[3] = __float_as_uint(t.w);
        }
        __syncthreads();

#pragma unroll
        for (int s = 0; s < 8; s++) {
            const int kc = s * 8 + lr;
            unsigned a0 = f2tf32(S[r0 * AS_LDS + kt * 64 + kc]);
            unsigned a1 = f2tf32(S[(r0 + 8) * AS_LDS + kt * 64 + kc]);
            unsigned a2 = f2tf32(S[r0 * AS_LDS + kt * 64 + kc + 4]);
            unsigned a3 = f2tf32(S[(r0 + 8) * AS_LDS + kt * 64 + kc + 4]);
#pragma unroll
            for (int nt = 0; nt < 4; nt++) {
                int c = wn * 32 + nt * 8 + lq;
                unsigned b0 = KVs[kc * AQ_LD + c];
                unsigned b1 = KVs[(kc + 4) * AQ_LD + c];
                asm volatile(
                    "mma.sync.aligned.m16n8k8.row.col.f32.tf32.tf32.f32 "
                    "{%0,%1,%2,%3}, {%4,%5,%6,%7}, {%8,%9}, {%0,%1,%2,%3};"
                    : "+f"(o[nt][0]), "+f"(o[nt][1]),
                      "+f"(o[nt][2]), "+f"(o[nt][3])
                    : "r"(a0), "r"(a1), "r"(a2), "r"(a3),
                      "r"(b0), "r"(b1));
            }
        }
    }

    float* xb = x + ((size_t)b * SEQ + qt * 64) * DMODEL + h * HDIM;
#pragma unroll
    for (int nt = 0; nt < 4; nt++) {
        int col = wn * 32 + nt * 8 + lr * 2;
        xb[(size_t)r0 * DMODEL + col]           += o[nt][0];
        xb[(size_t)r0 * DMODEL + col + 1]       += o[nt][1];
        xb[(size_t)(r0 + 8) * DMODEL + col]     += o[nt][2];
        xb[(size_t)(r0 + 8) * DMODEL + col + 1] += o[nt][3];
    }
}

// ---------------- launch ----------------------------------------------------
extern "C" void kernel_launch(void* const* d_in, const int* in_sizes, int n_in,
                              void* d_out, int out_size)
{
    const float* x_in = (const float*)d_in[0];
    const float* Wq = (const float*)d_in[1];
    const float* bq = (const float*)d_in[2];
    const float* Wk = (const float*)d_in[3];
    const float* bk = (const float*)d_in[4];
    const float* Wv = (const float*)d_in[5];
    const float* bv = (const float*)d_in[6];
    const float* g1 = (const float*)d_in[7];
    const float* be1 = (const float*)d_in[8];
    const float* g2 = (const float*)d_in[9];
    const float* be2 = (const float*)d_in[10];
    const float* W0 = (const float*)d_in[11];
    const float* b0 = (const float*)d_in[12];
    const float* W1 = (const float*)d_in[13];
    const float* b1 = (const float*)d_in[14];

    float* x = (float*)d_out;

    void *p_xln, *p_q, *p_k, *p_v, *p_h1;
    void *p_wq, *p_wk, *p_wv, *p_w0, *p_w1;
    cudaGetSymbolAddress(&p_xln, g_xln);
    cudaGetSymbolAddress(&p_q, g_q);
    cudaGetSymbolAddress(&p_k, g_k);
    cudaGetSymbolAddress(&p_v, g_v);
    cudaGetSymbolAddress(&p_h1, g_h1);
    cudaGetSymbolAddress(&p_wq, g_wq);
    cudaGetSymbolAddress(&p_wk, g_wk);
    cudaGetSymbolAddress(&p_wv, g_wv);
    cudaGetSymbolAddress(&p_w0, g_w0);
    cudaGetSymbolAddress(&p_w1, g_w1);
    float* xln = (float*)p_xln;
    float* q = (float*)p_q;
    float* k = (float*)p_k;
    float* v = (float*)p_v;
    float* h1 = (float*)p_h1;
    float* wq = (float*)p_wq;
    float* wk = (float*)p_wk;
    float* wv = (float*)p_wv;
    float* w0 = (float*)p_w0;
    float* w1 = (float*)p_w1;

    cudaFuncSetAttribute(attn_kernel, cudaFuncAttributeMaxDynamicSharedMemorySize,
                         ATTN_SMEM_BYTES);
    cudaFuncSetAttribute(tf32_gemm_qkv_kernel, cudaFuncAttributeMaxDynamicSharedMemorySize,
                         GEMM128_SMEM);
    cudaFuncSetAttribute(tf32_gemm_kernel<4,1>, cudaFuncAttributeMaxDynamicSharedMemorySize,
                         GEMM128_SMEM);
    cudaFuncSetAttribute(tf32_gemm_kernel<2,2>, cudaFuncAttributeMaxDynamicSharedMemorySize,
                         GEMM64_SMEM);

    cudaMemcpyAsync(x, x_in, (size_t)NTOK * DMODEL * sizeof(float),
                    cudaMemcpyDeviceToDevice, 0);

    // pre-round weights to tf32 (once per launch; inside the graph)
    const int nDD4 = DMODEL * DMODEL / 4;     // 147456
    const int nDF4 = DMODEL * FFDIM / 4;      // 589824
    cvt_kernel<<<(nDD4 + 255) / 256, 256>>>(Wq, wq, nDD4);
    cvt_kernel<<<(nDD4 + 255) / 256, 256>>>(Wk, wk, nDD4);
    cvt_kernel<<<(nDD4 + 255) / 256, 256>>>(Wv, wv, nDD4);
    cvt_kernel<<<(nDF4 + 255) / 256, 256>>>(W0, w0, nDF4);
    cvt_kernel<<<(nDF4 + 255) / 256, 256>>>(W1, w1, nDF4);

    const dim3 gemmQKV(DMODEL / BN, NTOK / 128, 3);  // (6,16,3)
    const dim3 gemmFF1(FFDIM / BN, NTOK / 128);      // (24,16)
    const dim3 gemmFF2(DMODEL / BN, NTOK / 64);      // (6,32)
    const dim3 attnGrid(SEQ / 64, BATCH * NHEAD);    // (8,48)

    for (int blk = 0; blk < NBLOCKS; blk++) {
        ln_kernel<<<NTOK, 256>>>(x, g1, be1, xln);
        tf32_gemm_qkv_kernel<<<gemmQKV, 256, GEMM128_SMEM>>>(
            xln, wq, wk, wv, bq, bk, bv, q, k, v);
        attn_kernel<<<attnGrid, 256, ATTN_SMEM_BYTES>>>(q, k, v, x);
        ln_kernel<<<NTOK, 256>>>(x, g2, be2, xln);
        tf32_gemm_kernel<4,1><<<gemmFF1, 256, GEMM128_SMEM>>>(xln, w0, b0, h1, FFDIM, DMODEL);
        tf32_gemm_kernel<2,2><<<gemmFF2, 256, GEMM64_SMEM>>>(h1, w1, b1, x, DMODEL, FFDIM);
    }
}

// round 7
// speedup vs baseline: 5.9587x; 1.5097x over previous
#include <cuda_runtime.h>
#include <cuda_fp16.h>
#include <math.h>
#include <stdint.h>

// Problem constants
#define BATCH 4
#define SEQ   512
#define DMODEL 768
#define FFDIM 3072
#define NHEAD 12
#define HDIM  64
#define NTOK  (BATCH*SEQ)          // 2048
#define NBLOCKS 12

// ---------------- scratch (device globals; no allocation allowed) -----------
__device__ __half g_xln[NTOK * DMODEL];
__device__ float  g_q  [NTOK * DMODEL];
__device__ float  g_k  [NTOK * DMODEL];
__device__ float  g_v  [NTOK * DMODEL];
__device__ __half g_h1 [NTOK * FFDIM];
// fp16, TRANSPOSED weights: wt[n][k] = half(W[k][n])
__device__ __half g_wqT[DMODEL * DMODEL];
__device__ __half g_wkT[DMODEL * DMODEL];
__device__ __half g_wvT[DMODEL * DMODEL];
__device__ __half g_w0T[FFDIM * DMODEL];    // [3072][768]
__device__ __half g_w1T[DMODEL * FFDIM];    // [768][3072]

__device__ __forceinline__ unsigned f2tf32(float f) {
    unsigned r;
    asm("cvt.rna.tf32.f32 %0, %1;" : "=r"(r) : "f"(f));
    return r;
}
__device__ __forceinline__ float f2tf32f(float f) {
    return __uint_as_float(f2tf32(f));
}
__device__ __forceinline__ void cpa16(unsigned dst, const void* src) {
    asm volatile("cp.async.cg.shared.global [%0], [%1], 16;\n" :: "r"(dst), "l"(src));
}
__device__ __forceinline__ void cpa_commit() {
    asm volatile("cp.async.commit_group;\n" ::: "memory");
}
template <int N>
__device__ __forceinline__ void cpa_wait() {
    asm volatile("cp.async.wait_group %0;\n" :: "n"(N) : "memory");
}
__device__ __forceinline__ unsigned smem_u32(const void* p) {
    unsigned r;
    asm("{ .reg .u64 t; cvta.to.shared.u64 t, %1; cvt.u32.u64 %0, t; }"
        : "=r"(r) : "l"(p));
    return r;
}

// ---------------- transpose + fp16 convert (once per launch) ----------------
// src [R][C] fp32 -> dst [C][R] fp16.  block (32,8), grid (C/32, R/32).
__global__ __launch_bounds__(256) void transpose_h_kernel(
    const float* __restrict__ src, __half* __restrict__ dst, int R, int C)
{
    __shared__ float t[32][33];
    const int c0 = blockIdx.x * 32, r0 = blockIdx.y * 32;
    const int tx = threadIdx.x, ty = threadIdx.y;
#pragma unroll
    for (int i = 0; i < 4; i++)
        t[ty + 8 * i][tx] = src[(size_t)(r0 + ty + 8 * i) * C + c0 + tx];
    __syncthreads();
#pragma unroll
    for (int i = 0; i < 4; i++)
        dst[(size_t)(c0 + ty + 8 * i) * R + r0 + tx] = __float2half_rn(t[tx][ty + 8 * i]);
}

// ---------------- LayerNorm: one block per row; outputs fp16 ----------------
__global__ __launch_bounds__(256) void ln_kernel(
    const float* __restrict__ x, const float* __restrict__ g,
    const float* __restrict__ be, __half* __restrict__ y)
{
    __shared__ float redS[8];
    __shared__ float redS2[8];
    const int r = blockIdx.x;
    const int tid = threadIdx.x;
    const float* xr = x + (size_t)r * DMODEL;

    float vals[3];
    float s = 0.f, s2 = 0.f;
#pragma unroll
    for (int c = 0; c < 3; c++) {
        float v = xr[tid + c * 256];
        vals[c] = v;
        s += v; s2 += v * v;
    }
#pragma unroll
    for (int o = 16; o > 0; o >>= 1) {
        s  += __shfl_xor_sync(0xffffffffu, s,  o);
        s2 += __shfl_xor_sync(0xffffffffu, s2, o);
    }
    const int wid = tid >> 5, lane = tid & 31;
    if (lane == 0) { redS[wid] = s; redS2[wid] = s2; }
    __syncthreads();
    if (tid < 32) {
        float a  = (tid < 8) ? redS [tid] : 0.f;
        float a2 = (tid < 8) ? redS2[tid] : 0.f;
#pragma unroll
        for (int o = 4; o > 0; o >>= 1) {
            a  += __shfl_xor_sync(0xffffffffu, a,  o);
            a2 += __shfl_xor_sync(0xffffffffu, a2, o);
        }
        if (tid == 0) { redS[0] = a; redS2[0] = a2; }
    }
    __syncthreads();
    const float mu  = redS[0]  * (1.f / DMODEL);
    const float var = redS2[0] * (1.f / DMODEL) - mu * mu;
    const float inv = rsqrtf(var + 1e-5f);
    __half* yr = y + (size_t)r * DMODEL;
#pragma unroll
    for (int c = 0; c < 3; c++) {
        int j = tid + c * 256;
        yr[j] = __float2half_rn((vals[c] - mu) * inv * g[j] + be[j]);
    }
}

// ===================== FP16 tensor-core GEMM ================================
// C[M,N] = act(A[M,K] @ W[K,N] + bias); A fp16 [M][K], BT=W^T fp16 [N][K].
// CTA tile (MT*32)x128xBK64; 8 warps 2x4; warp tile (MT*16)x32;
// mma m16n8k16 f16 -> f32.  3-stage cp.async, XOR-swizzled smem (u32 granule).
// MODE 1: gelu -> half store; MODE 2: float C += v; MODE 3: tf32-round float store.

#define BKH 64               // halfs per K chunk (= 32 u32 per row, 128 B)
#define NSTAGE 3

template <int MT, int MODE>
__device__ __forceinline__ void h_gemm_core(
    const __half* __restrict__ A, const __half* __restrict__ BT,
    const float* __restrict__ bias, void* __restrict__ Cv,
    int N, int K)
{
    constexpr int BMv  = MT * 32;          // 128 or 64
    constexpr int ASTG = BMv * 32;         // u32 per A stage
    constexpr int BSTG = 128 * 32;         // u32 per B stage (BN=128)

    extern __shared__ unsigned smemU[];
    unsigned* As = smemU;                    // [NSTAGE][ASTG]
    unsigned* Bs = smemU + NSTAGE * ASTG;    // [NSTAGE][BSTG]
    const unsigned asBase = smem_u32(As);
    const unsigned bsBase = smem_u32(Bs);

    const int tid  = threadIdx.x;
    const int lane = tid & 31;
    const int wid  = tid >> 5;
    const int wm   = wid >> 2;            // 0..1
    const int wn   = wid & 3;             // 0..3
    const int rowBase = blockIdx.y * BMv;
    const int colBase = blockIdx.x * 128;
    const int lq = lane >> 2;   // 0..7
    const int lr = lane & 3;    // 0..3

    auto issue = [&](int c) {
        const int st = c % NSTAGE;
        const int k0 = c * BKH;
#pragma unroll
        for (int i = 0; i < MT; i++) {       // BMv*8 16B-chunks
            int fi = tid + i * 256;
            int r = fi >> 3, c8 = fi & 7;
            unsigned u = (unsigned)(c8 * 4) ^ (((unsigned)r & 7u) << 2);
            cpa16(asBase + (st * ASTG + r * 32 + u) * 4u,
                  A + (size_t)(rowBase + r) * K + k0 + c8 * 8);
        }
#pragma unroll
        for (int i = 0; i < 4; i++) {        // 128*8 chunks
            int fi = tid + i * 256;
            int r = fi >> 3, c8 = fi & 7;
            unsigned u = (unsigned)(c8 * 4) ^ (((unsigned)r & 7u) << 2);
            cpa16(bsBase + (st * BSTG + r * 32 + u) * 4u,
                  BT + (size_t)(colBase + r) * K + k0 + c8 * 8);
        }
    };

    float acc[MT][4][4];
#pragma unroll
    for (int i = 0; i < MT; i++)
#pragma unroll
        for (int j = 0; j < 4; j++)
#pragma unroll
            for (int t = 0; t < 4; t++) acc[i][j][t] = 0.f;

    const int nch = K / BKH;
    issue(0); cpa_commit();
    issue(1); cpa_commit();

    for (int c = 0; c < nch; c++) {
        cpa_wait<1>();
        __syncthreads();

        if (c + 2 < nch) issue(c + 2);
        cpa_commit();

        const unsigned* Ab = As + (c % NSTAGE) * ASTG;
        const unsigned* Bb = Bs + (c % NSTAGE) * BSTG;
#pragma unroll
        for (int ks = 0; ks < 4; ks++) {
            const int i0 = ks * 8 + lr;          // u32 idx for k pair 2lr
            const int i1 = i0 + 4;               // k pair 2lr+8
            const unsigned swz = ((unsigned)lq & 7u) << 2;
            const int u0 = i0 ^ swz, u1 = i1 ^ swz;
            unsigned af[MT][4];
#pragma unroll
            for (int mt = 0; mt < MT; mt++) {
                int r0 = wm * (MT * 16) + mt * 16 + lq;
                af[mt][0] = Ab[r0 * 32 + u0];
                af[mt][1] = Ab[(r0 + 8) * 32 + u0];
                af[mt][2] = Ab[r0 * 32 + u1];
                af[mt][3] = Ab[(r0 + 8) * 32 + u1];
            }
            unsigned bf[4][2];
#pragma unroll
            for (int nt = 0; nt < 4; nt++) {
                int cc = wn * 32 + nt * 8 + lq;
                bf[nt][0] = Bb[cc * 32 + u0];
                bf[nt][1] = Bb[cc * 32 + u1];
            }
#pragma unroll
            for (int mt = 0; mt < MT; mt++)
#pragma unroll
                for (int nt = 0; nt < 4; nt++) {
                    asm volatile(
                        "mma.sync.aligned.m16n8k16.row.col.f32.f16.f16.f32 "
                        "{%0,%1,%2,%3}, {%4,%5,%6,%7}, {%8,%9}, {%0,%1,%2,%3};"
                        : "+f"(acc[mt][nt][0]), "+f"(acc[mt][nt][1]),
                          "+f"(acc[mt][nt][2]), "+f"(acc[mt][nt][3])
                        : "r"(af[mt][0]), "r"(af[mt][1]),
                          "r"(af[mt][2]), "r"(af[mt][3]),
                          "r"(bf[nt][0]), "r"(bf[nt][1]));
                }
        }
        __syncthreads();
    }

    // epilogue
#pragma unroll
    for (int mt = 0; mt < MT; mt++) {
        int row = rowBase + wm * (MT * 16) + mt * 16 + lq;
#pragma unroll
        for (int nt = 0; nt < 4; nt++) {
            int col = colBase + wn * 32 + nt * 8 + lr * 2;
            float b0 = bias[col], b1 = bias[col + 1];
            float v00 = acc[mt][nt][0] + b0;
            float v01 = acc[mt][nt][1] + b1;
            float v10 = acc[mt][nt][2] + b0;
            float v11 = acc[mt][nt][3] + b1;
            if (MODE == 1) {
                // exact gelu, store half
                v00 = 0.5f * v00 * (1.0f + erff(v00 * 0.70710678118654752f));
                v01 = 0.5f * v01 * (1.0f + erff(v01 * 0.70710678118654752f));
                v10 = 0.5f * v10 * (1.0f + erff(v10 * 0.70710678118654752f));
                v11 = 0.5f * v11 * (1.0f + erff(v11 * 0.70710678118654752f));
                __half* C = (__half*)Cv;
                *(__half2*)(C + (size_t)row * N + col) =
                    __floats2half2_rn(v00, v01);
                *(__half2*)(C + (size_t)(row + 8) * N + col) =
                    __floats2half2_rn(v10, v11);
            } else if (MODE == 2) {
                float* C = (float*)Cv;
                float2 c0 = *(const float2*)(C + (size_t)row * N + col);
                float2 c1 = *(const float2*)(C + (size_t)(row + 8) * N + col);
                c0.x += v00; c0.y += v01;
                c1.x += v10; c1.y += v11;
                *(float2*)(C + (size_t)row * N + col) = c0;
                *(float2*)(C + (size_t)(row + 8) * N + col) = c1;
            } else {  // MODE 3: tf32-rounded float (feeds tf32 attention)
                float* C = (float*)Cv;
                float2 o0 = make_float2(f2tf32f(v00), f2tf32f(v01));
                float2 o1 = make_float2(f2tf32f(v10), f2tf32f(v11));
                *(float2*)(C + (size_t)row * N + col) = o0;
                *(float2*)(C + (size_t)(row + 8) * N + col) = o1;
            }
        }
    }
}

template <int MT, int MODE>
__global__ __launch_bounds__(256) void h_gemm_kernel(
    const __half* __restrict__ A, const __half* __restrict__ BT,
    const float* __restrict__ bias, void* __restrict__ C, int N, int K)
{
    h_gemm_core<MT, MODE>(A, BT, bias, C, N, K);
}

__global__ __launch_bounds__(256) void h_gemm_qkv_kernel(
    const __half* __restrict__ A,
    const __half* __restrict__ WqT, const __half* __restrict__ WkT,
    const __half* __restrict__ WvT,
    const float* __restrict__ bq, const float* __restrict__ bk,
    const float* __restrict__ bv,
    float* __restrict__ q, float* __restrict__ k, float* __restrict__ v)
{
    const __half* BT; const float* bias; float* C;
    if (blockIdx.z == 0)      { BT = WqT; bias = bq; C = q; }
    else if (blockIdx.z == 1) { BT = WkT; bias = bk; C = k; }
    else                      { BT = WvT; bias = bv; C = v; }
    h_gemm_core<4, 3>(A, BT, bias, C, DMODEL, DMODEL);
}

#define HGEMM_SMEM_128 (NSTAGE * (128*32 + 128*32) * 4)   // 98304
#define HGEMM_SMEM_64  (NSTAGE * (64*32  + 128*32) * 4)   // 73728

// ======================= TF32 mma.sync attention (unchanged) ================
#define AQ_LD 68
#define AS_LDS 516
#define ATTN_SMEM_WORDS (2 * 64 * AQ_LD + 64 * AS_LDS)
#define ATTN_SMEM_BYTES (ATTN_SMEM_WORDS * 4)      // 166912

__global__ __launch_bounds__(256) void attn_kernel(
    const float* __restrict__ q, const float* __restrict__ k,
    const float* __restrict__ v, float* __restrict__ x)
{
    extern __shared__ unsigned smA[];
    unsigned* Qs  = smA;                    // [64][68]
    unsigned* KVs = smA + 64 * AQ_LD;       // [64][68]
    float*    S   = (float*)(smA + 2 * 64 * AQ_LD);   // [64][516]

    const int tid = threadIdx.x;
    const int lane = tid & 31;
    const int wid = tid >> 5;
    const int wm = wid >> 1;                // 0..3
    const int wn = wid & 1;                 // 0..1
    const int lq = lane >> 2;
    const int lr = lane & 3;

    const int qt = blockIdx.x;
    const int bh = blockIdx.y;
    const int b = bh / NHEAD, h = bh % NHEAD;

    const float* qb = q + ((size_t)b * SEQ + qt * 64) * DMODEL + h * HDIM;
    const float* kb = k + (size_t)b * SEQ * DMODEL + h * HDIM;
    const float* vb = v + (size_t)b * SEQ * DMODEL + h * HDIM;

#pragma unroll
    for (int c = 0; c < 4; c++) {
        int fi = tid + c * 256;
        int row = fi >> 4, col4 = fi & 15;
        float4 t = *(const float4*)(qb + (size_t)row * DMODEL + col4 * 4);
        unsigned* d = Qs + row * AQ_LD + col4 * 4;
        d[0] = __float_as_uint(t.x); d[1] = __float_as_uint(t.y);
        d[2] = __float_as_uint(t.z); d[3] = __float_as_uint(t.w);
    }

    for (int kt = 0; kt < 8; kt++) {
        __syncthreads();
#pragma unroll
        for (int c = 0; c < 4; c++) {
            int fi = tid + c * 256;
            int row = fi >> 4, col4 = fi & 15;
            float4 t = *(const float4*)(kb + (size_t)(kt * 64 + row) * DMODEL + col4 * 4);
            unsigned* d = KVs + row * AQ_LD + col4 * 4;
            d[0] = __float_as_uint(t.x); d[1] = __float_as_uint(t.y);
            d[2] = __float_as_uint(t.z); d[3] = __float_as_uint(t.w);
        }
        __syncthreads();

        float acc[4][4];
#pragma unroll
        for (int nt = 0; nt < 4; nt++)
#pragma unroll
            for (int t = 0; t < 4; t++) acc[nt][t] = 0.f;

        const int r0 = wm * 16 + lq;
#pragma unroll
        for (int s = 0; s < 8; s++) {
            const int kc = s * 8 + lr;
            unsigned a0 = Qs[r0 * AQ_LD + kc];
            unsigned a1 = Qs[(r0 + 8) * AQ_LD + kc];
            unsigned a2 = Qs[r0 * AQ_LD + kc + 4];
            unsigned a3 = Qs[(r0 + 8) * AQ_LD + kc + 4];
#pragma unroll
            for (int nt = 0; nt < 4; nt++) {
                int c = wn * 32 + nt * 8 + lq;
                unsigned b0 = KVs[c * AQ_LD + kc];
                unsigned b1 = KVs[c * AQ_LD + kc + 4];
                asm volatile(
                    "mma.sync.aligned.m16n8k8.row.col.f32.tf32.tf32.f32 "
                    "{%0,%1,%2,%3}, {%4,%5,%6,%7}, {%8,%9}, {%0,%1,%2,%3};"
                    : "+f"(acc[nt][0]), "+f"(acc[nt][1]),
                      "+f"(acc[nt][2]), "+f"(acc[nt][3])
                    : "r"(a0), "r"(a1), "r"(a2), "r"(a3),
                      "r"(b0), "r"(b1));
            }
        }
#pragma unroll
        for (int nt = 0; nt < 4; nt++) {
            int col = kt * 64 + wn * 32 + nt * 8 + lr * 2;
            S[r0 * AS_LDS + col]           = acc[nt][0] * 0.125f;
            S[r0 * AS_LDS + col + 1]       = acc[nt][1] * 0.125f;
            S[(r0 + 8) * AS_LDS + col]     = acc[nt][2] * 0.125f;
            S[(r0 + 8) * AS_LDS + col + 1] = acc[nt][3] * 0.125f;
        }
    }
    __syncthreads();

    for (int rr = 0; rr < 8; rr++) {
        float* Sr = S + (wid * 8 + rr) * AS_LDS;
        float m = -1e30f;
        for (int j = lane; j < SEQ; j += 32) m = fmaxf(m, Sr[j]);
#pragma unroll
        for (int o = 16; o > 0; o >>= 1) m = fmaxf(m, __shfl_xor_sync(0xffffffffu, m, o));
        float s = 0.f;
        for (int j = lane; j < SEQ; j += 32) {
            float e = __expf(Sr[j] - m);
            Sr[j] = e;
            s += e;
        }
#pragma unroll
        for (int o = 16; o > 0; o >>= 1) s += __shfl_xor_sync(0xffffffffu, s, o);
        float inv = 1.f / s;
        for (int j = lane; j < SEQ; j += 32) Sr[j] *= inv;
    }

    float o[4][4];
#pragma unroll
    for (int nt = 0; nt < 4; nt++)
#pragma unroll
        for (int t = 0; t < 4; t++) o[nt][t] = 0.f;

    const int r0 = wm * 16 + lq;
    for (int kt = 0; kt < 8; kt++) {
        __syncthreads();
#pragma unroll
        for (int c = 0; c < 4; c++) {
            int fi = tid + c * 256;
            int row = fi >> 4, col4 = fi & 15;
            float4 t = *(const float4*)(vb + (size_t)(kt * 64 + row) * DMODEL + col4 * 4);
            unsigned* d = KVs + row * AQ_LD + col4 * 4;
            d[0] = __float_as_uint(t.x); d[1] = __float_as_uint(t.y);
            d[2] = __float_as_uint(t.z); d[3] = __float_as_uint(t.w);
        }
        __syncthreads();

#pragma unroll
        for (int s = 0; s < 8; s++) {
            const int kc = s * 8 + lr;
            unsigned a0 = f2tf32(S[r0 * AS_LDS + kt * 64 + kc]);
            unsigned a1 = f2tf32(S[(r0 + 8) * AS_LDS + kt * 64 + kc]);
            unsigned a2 = f2tf32(S[r0 * AS_LDS + kt * 64 + kc + 4]);
            unsigned a3 = f2tf32(S[(r0 + 8) * AS_LDS + kt * 64 + kc + 4]);
#pragma unroll
            for (int nt = 0; nt < 4; nt++) {
                int c = wn * 32 + nt * 8 + lq;
                unsigned b0 = KVs[kc * AQ_LD + c];
                unsigned b1 = KVs[(kc + 4) * AQ_LD + c];
                asm volatile(
                    "mma.sync.aligned.m16n8k8.row.col.f32.tf32.tf32.f32 "
                    "{%0,%1,%2,%3}, {%4,%5,%6,%7}, {%8,%9}, {%0,%1,%2,%3};"
                    : "+f"(o[nt][0]), "+f"(o[nt][1]),
                      "+f"(o[nt][2]), "+f"(o[nt][3])
                    : "r"(a0), "r"(a1), "r"(a2), "r"(a3),
                      "r"(b0), "r"(b1));
            }
        }
    }

    float* xb = x + ((size_t)b * SEQ + qt * 64) * DMODEL + h * HDIM;
#pragma unroll
    for (int nt = 0; nt < 4; nt++) {
        int col = wn * 32 + nt * 8 + lr * 2;
        xb[(size_t)r0 * DMODEL + col]           += o[nt][0];
        xb[(size_t)r0 * DMODEL + col + 1]       += o[nt][1];
        xb[(size_t)(r0 + 8) * DMODEL + col]     += o[nt][2];
        xb[(size_t)(r0 + 8) * DMODEL + col + 1] += o[nt][3];
    }
}

// ---------------- launch ----------------------------------------------------
extern "C" void kernel_launch(void* const* d_in, const int* in_sizes, int n_in,
                              void* d_out, int out_size)
{
    const float* x_in = (const float*)d_in[0];
    const float* Wq = (const float*)d_in[1];
    const float* bq = (const float*)d_in[2];
    const float* Wk = (const float*)d_in[3];
    const float* bk = (const float*)d_in[4];
    const float* Wv = (const float*)d_in[5];
    const float* bv = (const float*)d_in[6];
    const float* g1 = (const float*)d_in[7];
    const float* be1 = (const float*)d_in[8];
    const float* g2 = (const float*)d_in[9];
    const float* be2 = (const float*)d_in[10];
    const float* W0 = (const float*)d_in[11];
    const float* b0 = (const float*)d_in[12];
    const float* W1 = (const float*)d_in[13];
    const float* b1 = (const float*)d_in[14];

    float* x = (float*)d_out;

    void *p_xln, *p_q, *p_k, *p_v, *p_h1;
    void *p_wq, *p_wk, *p_wv, *p_w0, *p_w1;
    cudaGetSymbolAddress(&p_xln, g_xln);
    cudaGetSymbolAddress(&p_q, g_q);
    cudaGetSymbolAddress(&p_k, g_k);
    cudaGetSymbolAddress(&p_v, g_v);
    cudaGetSymbolAddress(&p_h1, g_h1);
    cudaGetSymbolAddress(&p_wq, g_wqT);
    cudaGetSymbolAddress(&p_wk, g_wkT);
    cudaGetSymbolAddress(&p_wv, g_wvT);
    cudaGetSymbolAddress(&p_w0, g_w0T);
    cudaGetSymbolAddress(&p_w1, g_w1T);
    __half* xln = (__half*)p_xln;
    float* q = (float*)p_q;
    float* k = (float*)p_k;
    float* v = (float*)p_v;
    __half* h1 = (__half*)p_h1;
    __half* wqT = (__half*)p_wq;
    __half* wkT = (__half*)p_wk;
    __half* wvT = (__half*)p_wv;
    __half* w0T = (__half*)p_w0;
    __half* w1T = (__half*)p_w1;

    cudaFuncSetAttribute(attn_kernel, cudaFuncAttributeMaxDynamicSharedMemorySize,
                         ATTN_SMEM_BYTES);
    cudaFuncSetAttribute(h_gemm_qkv_kernel, cudaFuncAttributeMaxDynamicSharedMemorySize,
                         HGEMM_SMEM_128);
    cudaFuncSetAttribute(h_gemm_kernel<4,1>, cudaFuncAttributeMaxDynamicSharedMemorySize,
                         HGEMM_SMEM_128);
    cudaFuncSetAttribute(h_gemm_kernel<2,2>, cudaFuncAttributeMaxDynamicSharedMemorySize,
                         HGEMM_SMEM_64);

    cudaMemcpyAsync(x, x_in, (size_t)NTOK * DMODEL * sizeof(float),
                    cudaMemcpyDeviceToDevice, 0);

    // transpose + fp16 convert weights (once per launch; captured in graph)
    dim3 tb(32, 8);
    transpose_h_kernel<<<dim3(DMODEL/32, DMODEL/32), tb>>>(Wq, wqT, DMODEL, DMODEL);
    transpose_h_kernel<<<dim3(DMODEL/32, DMODEL/32), tb>>>(Wk, wkT, DMODEL, DMODEL);
    transpose_h_kernel<<<dim3(DMODEL/32, DMODEL/32), tb>>>(Wv, wvT, DMODEL, DMODEL);
    transpose_h_kernel<<<dim3(FFDIM/32, DMODEL/32), tb>>>(W0, w0T, DMODEL, FFDIM);
    transpose_h_kernel<<<dim3(DMODEL/32, FFDIM/32), tb>>>(W1, w1T, FFDIM, DMODEL);

    const dim3 gemmQKV(DMODEL / 128, NTOK / 128, 3);  // (6,16,3)
    const dim3 gemmFF1(FFDIM / 128, NTOK / 128);      // (24,16)
    const dim3 gemmFF2(DMODEL / 128, NTOK / 64);      // (6,32)
    const dim3 attnGrid(SEQ / 64, BATCH * NHEAD);     // (8,48)

    for (int blk = 0; blk < NBLOCKS; blk++) {
        ln_kernel<<<NTOK, 256>>>(x, g1, be1, xln);
        h_gemm_qkv_kernel<<<gemmQKV, 256, HGEMM_SMEM_128>>>(
            xln, wqT, wkT, wvT, bq, bk, bv, q, k, v);
        attn_kernel<<<attnGrid, 256, ATTN_SMEM_BYTES>>>(q, k, v, x);
        ln_kernel<<<NTOK, 256>>>(x, g2, be2, xln);
        h_gemm_kernel<4,1><<<gemmFF1, 256, HGEMM_SMEM_128>>>(
            xln, w0T, b0, (void*)h1, FFDIM, DMODEL);
        h_gemm_kernel<2,2><<<gemmFF2, 256, HGEMM_SMEM_64>>>(
            h1, w1T, b1, (void*)x, DMODEL, FFDIM);
    }
}

// round 8
// speedup vs baseline: 6.4778x; 1.0871x over previous
#include <cuda_runtime.h>
#include <cuda_fp16.h>
#include <math.h>
#include <stdint.h>

// Problem constants
#define BATCH 4
#define SEQ   512
#define DMODEL 768
#define FFDIM 3072
#define NHEAD 12
#define HDIM  64
#define NTOK  (BATCH*SEQ)          // 2048
#define NBLOCKS 12

// ---------------- scratch (device globals; no allocation allowed) -----------
__device__ __half g_xln[NTOK * DMODEL];
__device__ __half g_q  [NTOK * DMODEL];
__device__ __half g_k  [NTOK * DMODEL];
__device__ __half g_v  [NTOK * DMODEL];
__device__ __half g_h1 [NTOK * FFDIM];
// fp16, TRANSPOSED weights: wt[n][k] = half(W[k][n])
__device__ __half g_wqT[DMODEL * DMODEL];
__device__ __half g_wkT[DMODEL * DMODEL];
__device__ __half g_wvT[DMODEL * DMODEL];
__device__ __half g_w0T[FFDIM * DMODEL];    // [3072][768]
__device__ __half g_w1T[DMODEL * FFDIM];    // [768][3072]

__device__ __forceinline__ void cpa16(unsigned dst, const void* src) {
    asm volatile("cp.async.cg.shared.global [%0], [%1], 16;\n" :: "r"(dst), "l"(src));
}
__device__ __forceinline__ void cpa_commit() {
    asm volatile("cp.async.commit_group;\n" ::: "memory");
}
template <int N>
__device__ __forceinline__ void cpa_wait() {
    asm volatile("cp.async.wait_group %0;\n" :: "n"(N) : "memory");
}
__device__ __forceinline__ unsigned smem_u32(const void* p) {
    unsigned r;
    asm("{ .reg .u64 t; cvta.to.shared.u64 t, %1; cvt.u32.u64 %0, t; }"
        : "=r"(r) : "l"(p));
    return r;
}
__device__ __forceinline__ unsigned packh2(float a, float b) {
    __half2 h = __floats2half2_rn(a, b);
    return *(unsigned*)&h;
}

#define HMMA16816(acc, a0, a1, a2, a3, b0, b1) \
    asm volatile( \
        "mma.sync.aligned.m16n8k16.row.col.f32.f16.f16.f32 " \
        "{%0,%1,%2,%3}, {%4,%5,%6,%7}, {%8,%9}, {%0,%1,%2,%3};" \
        : "+f"((acc)[0]), "+f"((acc)[1]), "+f"((acc)[2]), "+f"((acc)[3]) \
        : "r"(a0), "r"(a1), "r"(a2), "r"(a3), "r"(b0), "r"(b1))

// ---------------- transpose + fp16 convert (once per launch) ----------------
__global__ __launch_bounds__(256) void transpose_h_kernel(
    const float* __restrict__ src, __half* __restrict__ dst, int R, int C)
{
    __shared__ float t[32][33];
    const int c0 = blockIdx.x * 32, r0 = blockIdx.y * 32;
    const int tx = threadIdx.x, ty = threadIdx.y;
#pragma unroll
    for (int i = 0; i < 4; i++)
        t[ty + 8 * i][tx] = src[(size_t)(r0 + ty + 8 * i) * C + c0 + tx];
    __syncthreads();
#pragma unroll
    for (int i = 0; i < 4; i++)
        dst[(size_t)(c0 + ty + 8 * i) * R + r0 + tx] = __float2half_rn(t[tx][ty + 8 * i]);
}

// ---------------- LayerNorm: warp per row; outputs fp16 ---------------------
__global__ __launch_bounds__(256) void ln_kernel(
    const float* __restrict__ x, const float* __restrict__ g,
    const float* __restrict__ be, __half* __restrict__ y)
{
    const int wid = threadIdx.x >> 5, lane = threadIdx.x & 31;
    const int r = blockIdx.x * 8 + wid;
    const float* xr = x + (size_t)r * DMODEL;

    float4 v[6];
    float s = 0.f, s2 = 0.f;
#pragma unroll
    for (int i = 0; i < 6; i++) {
        v[i] = *(const float4*)(xr + (i * 32 + lane) * 4);
        s  += v[i].x + v[i].y + v[i].z + v[i].w;
        s2 += v[i].x * v[i].x + v[i].y * v[i].y + v[i].z * v[i].z + v[i].w * v[i].w;
    }
#pragma unroll
    for (int o = 16; o > 0; o >>= 1) {
        s  += __shfl_xor_sync(0xffffffffu, s,  o);
        s2 += __shfl_xor_sync(0xffffffffu, s2, o);
    }
    const float mu  = s  * (1.f / DMODEL);
    const float var = s2 * (1.f / DMODEL) - mu * mu;
    const float inv = rsqrtf(var + 1e-5f);
    __half* yr = y + (size_t)r * DMODEL;
#pragma unroll
    for (int i = 0; i < 6; i++) {
        const int col = (i * 32 + lane) * 4;
        float4 gg = *(const float4*)(g + col);
        float4 bb = *(const float4*)(be + col);
        unsigned p0 = packh2((v[i].x - mu) * inv * gg.x + bb.x,
                             (v[i].y - mu) * inv * gg.y + bb.y);
        unsigned p1 = packh2((v[i].z - mu) * inv * gg.z + bb.z,
                             (v[i].w - mu) * inv * gg.w + bb.w);
        uint2 o; o.x = p0; o.y = p1;
        *(uint2*)(yr + col) = o;
    }
}

// ===================== FP16 tensor-core GEMM ================================
// C[M,N] = act(A[M,K] @ W[K,N] + bias); A fp16 [M][K], BT=W^T fp16 [N][K].
// CTA tile (MT*32)x128xBK64; 8 warps 2x4; warp tile (MT*16)x32; mma m16n8k16.
// MODE 0: half store; MODE 1: gelu -> half store; MODE 2: float C += v.
#define BKH 64
#define NSTAGE 3

template <int MT, int MODE>
__device__ __forceinline__ void h_gemm_core(
    const __half* __restrict__ A, const __half* __restrict__ BT,
    const float* __restrict__ bias, void* __restrict__ Cv,
    int N, int K)
{
    constexpr int BMv  = MT * 32;
    constexpr int ASTG = BMv * 32;
    constexpr int BSTG = 128 * 32;

    extern __shared__ unsigned smemU[];
    unsigned* As = smemU;
    unsigned* Bs = smemU + NSTAGE * ASTG;
    const unsigned asBase = smem_u32(As);
    const unsigned bsBase = smem_u32(Bs);

    const int tid  = threadIdx.x;
    const int lane = tid & 31;
    const int wid  = tid >> 5;
    const int wm   = wid >> 2;
    const int wn   = wid & 3;
    const int rowBase = blockIdx.y * BMv;
    const int colBase = blockIdx.x * 128;
    const int lq = lane >> 2;
    const int lr = lane & 3;

    auto issue = [&](int c) {
        const int st = c % NSTAGE;
        const int k0 = c * BKH;
#pragma unroll
        for (int i = 0; i < MT; i++) {
            int fi = tid + i * 256;
            int r = fi >> 3, c8 = fi & 7;
            unsigned u = (unsigned)(c8 * 4) ^ (((unsigned)r & 7u) << 2);
            cpa16(asBase + (st * ASTG + r * 32 + u) * 4u,
                  A + (size_t)(rowBase + r) * K + k0 + c8 * 8);
        }
#pragma unroll
        for (int i = 0; i < 4; i++) {
            int fi = tid + i * 256;
            int r = fi >> 3, c8 = fi & 7;
            unsigned u = (unsigned)(c8 * 4) ^ (((unsigned)r & 7u) << 2);
            cpa16(bsBase + (st * BSTG + r * 32 + u) * 4u,
                  BT + (size_t)(colBase + r) * K + k0 + c8 * 8);
        }
    };

    float acc[MT][4][4];
#pragma unroll
    for (int i = 0; i < MT; i++)
#pragma unroll
        for (int j = 0; j < 4; j++)
#pragma unroll
            for (int t = 0; t < 4; t++) acc[i][j][t] = 0.f;

    const int nch = K / BKH;
    issue(0); cpa_commit();
    issue(1); cpa_commit();

    for (int c = 0; c < nch; c++) {
        cpa_wait<1>();
        __syncthreads();
        if (c + 2 < nch) issue(c + 2);
        cpa_commit();

        const unsigned* Ab = As + (c % NSTAGE) * ASTG;
        const unsigned* Bb = Bs + (c % NSTAGE) * BSTG;
        const unsigned swz = ((unsigned)lq & 7u) << 2;
#pragma unroll
        for (int ks = 0; ks < 4; ks++) {
            const int i0 = ks * 8 + lr;
            const int u0 = i0 ^ swz, u1 = (i0 + 4) ^ swz;
            unsigned af[MT][4];
#pragma unroll
            for (int mt = 0; mt < MT; mt++) {
                int r0 = wm * (MT * 16) + mt * 16 + lq;
                af[mt][0] = Ab[r0 * 32 + u0];
                af[mt][1] = Ab[(r0 + 8) * 32 + u0];
                af[mt][2] = Ab[r0 * 32 + u1];
                af[mt][3] = Ab[(r0 + 8) * 32 + u1];
            }
#pragma unroll
            for (int nt = 0; nt < 4; nt++) {
                int cc = wn * 32 + nt * 8 + lq;
                unsigned b0 = Bb[cc * 32 + u0];
                unsigned b1 = Bb[cc * 32 + u1];
#pragma unroll
                for (int mt = 0; mt < MT; mt++)
                    HMMA16816(acc[mt][nt], af[mt][0], af[mt][1], af[mt][2], af[mt][3], b0, b1);
            }
        }
        __syncthreads();
    }

#pragma unroll
    for (int mt = 0; mt < MT; mt++) {
        int row = rowBase + wm * (MT * 16) + mt * 16 + lq;
#pragma unroll
        for (int nt = 0; nt < 4; nt++) {
            int col = colBase + wn * 32 + nt * 8 + lr * 2;
            float b0 = bias[col], b1 = bias[col + 1];
            float v00 = acc[mt][nt][0] + b0;
            float v01 = acc[mt][nt][1] + b1;
            float v10 = acc[mt][nt][2] + b0;
            float v11 = acc[mt][nt][3] + b1;
            if (MODE == 1) {
                v00 = 0.5f * v00 * (1.0f + erff(v00 * 0.70710678118654752f));
                v01 = 0.5f * v01 * (1.0f + erff(v01 * 0.70710678118654752f));
                v10 = 0.5f * v10 * (1.0f + erff(v10 * 0.70710678118654752f));
                v11 = 0.5f * v11 * (1.0f + erff(v11 * 0.70710678118654752f));
            }
            if (MODE == 0 || MODE == 1) {
                __half* C = (__half*)Cv;
                *(unsigned*)(C + (size_t)row * N + col)       = packh2(v00, v01);
                *(unsigned*)(C + (size_t)(row + 8) * N + col) = packh2(v10, v11);
            } else {
                float* C = (float*)Cv;
                float2 c0 = *(const float2*)(C + (size_t)row * N + col);
                float2 c1 = *(const float2*)(C + (size_t)(row + 8) * N + col);
                c0.x += v00; c0.y += v01;
                c1.x += v10; c1.y += v11;
                *(float2*)(C + (size_t)row * N + col) = c0;
                *(float2*)(C + (size_t)(row + 8) * N + col) = c1;
            }
        }
    }
}

template <int MT, int MODE>
__global__ __launch_bounds__(256) void h_gemm_kernel(
    const __half* __restrict__ A, const __half* __restrict__ BT,
    const float* __restrict__ bias, void* __restrict__ C, int N, int K)
{
    h_gemm_core<MT, MODE>(A, BT, bias, C, N, K);
}

__global__ __launch_bounds__(256) void h_gemm_qkv_kernel(
    const __half* __restrict__ A,
    const __half* __restrict__ WqT, const __half* __restrict__ WkT,
    const __half* __restrict__ WvT,
    const float* __restrict__ bq, const float* __restrict__ bk,
    const float* __restrict__ bv,
    __half* __restrict__ q, __half* __restrict__ k, __half* __restrict__ v)
{
    const __half* BT; const float* bias; __half* C;
    if (blockIdx.z == 0)      { BT = WqT; bias = bq; C = q; }
    else if (blockIdx.z == 1) { BT = WkT; bias = bk; C = k; }
    else                      { BT = WvT; bias = bv; C = v; }
    h_gemm_core<4, 0>(A, BT, bias, (void*)C, DMODEL, DMODEL);
}

#define HGEMM_SMEM_128 (NSTAGE * (128*32 + 128*32) * 4)   // 98304
#define HGEMM_SMEM_64  (NSTAGE * (64*32  + 128*32) * 4)   // 73728

// ===================== FP16 tensor-core attention ===========================
// CTA: 64 q-rows x 512 keys; 8 warps 4(row)x2(col).
// Smem (u32): Qs[2048] (reused as Vt), Ks[2048], Stg[64*33], Inv[64], S[64*516].
#define QS_OFF  0
#define KS_OFF  2048
#define STG_OFF 4096
#define INV_OFF (4096 + 64*33)          // 6208
#define S_OFF   (INV_OFF + 64)          // 6272
#define AS_LDS  516
#define ATTN_SMEM_BYTES ((S_OFF + 64 * AS_LDS) * 4)   // 157184

__global__ __launch_bounds__(256) void attn_kernel(
    const __half* __restrict__ q, const __half* __restrict__ k,
    const __half* __restrict__ v, float* __restrict__ x)
{
    extern __shared__ unsigned sm[];
    unsigned* Qs  = sm + QS_OFF;             // Q tile; later Vt
    unsigned* Ks  = sm + KS_OFF;
    __half*   Stg = (__half*)(sm + STG_OFF); // [64 keys][66 halves] stride 33 u32
    float*    Inv = (float*)(sm + INV_OFF);
    float*    S   = (float*)(sm + S_OFF);

    const int tid = threadIdx.x;
    const int lane = tid & 31;
    const int wid = tid >> 5;
    const int wm = wid >> 1;                // 0..3
    const int wn = wid & 1;                 // 0..1
    const int lq = lane >> 2;
    const int lr = lane & 3;
    const unsigned swz = (unsigned)lq << 2;

    const int qt = blockIdx.x;
    const int bh = blockIdx.y;
    const int b = bh / NHEAD, h = bh % NHEAD;

    const __half* qb = q + ((size_t)b * SEQ + qt * 64) * DMODEL + h * HDIM;
    const __half* kb = k + (size_t)b * SEQ * DMODEL + h * HDIM;
    const __half* vb = v + (size_t)b * SEQ * DMODEL + h * HDIM;

    // load Q tile (64x64 fp16, swizzled rows of 32 u32)
#pragma unroll
    for (int c = 0; c < 2; c++) {
        int fi = tid + c * 256;
        int row = fi >> 3, c8 = fi & 7;
        uint4 t = *(const uint4*)(qb + (size_t)row * DMODEL + c8 * 8);
        *(uint4*)&Qs[row * 32 + ((c8 * 4) ^ ((row & 7) << 2))] = t;
    }

    const int r0 = wm * 16 + lq;

    // --- Phase 1: S = (Q @ K^T) / 8 ---
    for (int kt = 0; kt < 8; kt++) {
        __syncthreads();
#pragma unroll
        for (int c = 0; c < 2; c++) {
            int fi = tid + c * 256;
            int row = fi >> 3, c8 = fi & 7;
            uint4 t = *(const uint4*)(kb + (size_t)(kt * 64 + row) * DMODEL + c8 * 8);
            *(uint4*)&Ks[row * 32 + ((c8 * 4) ^ ((row & 7) << 2))] = t;
        }
        __syncthreads();

        float acc[4][4];
#pragma unroll
        for (int nt = 0; nt < 4; nt++)
#pragma unroll
            for (int t = 0; t < 4; t++) acc[nt][t] = 0.f;

#pragma unroll
        for (int ks = 0; ks < 4; ks++) {
            const int i0 = ks * 8 + lr;
            const int u0 = i0 ^ swz, u1 = (i0 + 4) ^ swz;
            unsigned a0 = Qs[r0 * 32 + u0];
            unsigned a1 = Qs[(r0 + 8) * 32 + u0];
            unsigned a2 = Qs[r0 * 32 + u1];
            unsigned a3 = Qs[(r0 + 8) * 32 + u1];
#pragma unroll
            for (int nt = 0; nt < 4; nt++) {
                int cc = wn * 32 + nt * 8 + lq;
                unsigned b0 = Ks[cc * 32 + u0];
                unsigned b1 = Ks[cc * 32 + u1];
                HMMA16816(acc[nt], a0, a1, a2, a3, b0, b1);
            }
        }
#pragma unroll
        for (int nt = 0; nt < 4; nt++) {
            int col = kt * 64 + wn * 32 + nt * 8 + lr * 2;
            S[r0 * AS_LDS + col]           = acc[nt][0] * 0.125f;
            S[r0 * AS_LDS + col + 1]       = acc[nt][1] * 0.125f;
            S[(r0 + 8) * AS_LDS + col]     = acc[nt][2] * 0.125f;
            S[(r0 + 8) * AS_LDS + col + 1] = acc[nt][3] * 0.125f;
        }
    }
    __syncthreads();

    // --- softmax: max + exp/sum passes; 1/sum saved, scale folded into PV ---
    for (int rr = 0; rr < 8; rr++) {
        const int row = wid * 8 + rr;
        float* Sr = S + row * AS_LDS;
        float m = -1e30f;
        for (int j = lane; j < SEQ; j += 32) m = fmaxf(m, Sr[j]);
#pragma unroll
        for (int o = 16; o > 0; o >>= 1) m = fmaxf(m, __shfl_xor_sync(0xffffffffu, m, o));
        float s = 0.f;
        for (int j = lane; j < SEQ; j += 32) {
            float e = __expf(Sr[j] - m);
            Sr[j] = e;
            s += e;
        }
#pragma unroll
        for (int o = 16; o > 0; o >>= 1) s += __shfl_xor_sync(0xffffffffu, s, o);
        if (lane == 0) Inv[row] = 1.f / s;
    }
    __syncthreads();

    const float invA = Inv[r0];
    const float invB = Inv[r0 + 8];

    // --- Phase 2: O = P @ V ---
    float o[4][4];
#pragma unroll
    for (int nt = 0; nt < 4; nt++)
#pragma unroll
        for (int t = 0; t < 4; t++) o[nt][t] = 0.f;

    for (int kt = 0; kt < 8; kt++) {
        // load V tile [key][dim] into staging (stride 33 u32)
#pragma unroll
        for (int c = 0; c < 2; c++) {
            int fi = tid + c * 256;
            int row = fi >> 3, c8 = fi & 7;
            uint4 t = *(const uint4*)(vb + (size_t)(kt * 64 + row) * DMODEL + c8 * 8);
            unsigned* dst = (unsigned*)Stg + row * 33 + c8 * 4;
            dst[0] = t.x; dst[1] = t.y; dst[2] = t.z; dst[3] = t.w;
        }
        __syncthreads();   // staging ready; prev-iter mma done -> Vt writable
        // transpose -> Vt[dim][keypair u32] (in Qs region, swizzled)
#pragma unroll
        for (int i = 0; i < 8; i++) {
            int linear = tid + i * 256;           // 0..2047
            int jp = linear & 31, d = linear >> 5;
            __half h0 = Stg[(2 * jp) * 66 + d];
            __half h1 = Stg[(2 * jp + 1) * 66 + d];
            __half2 hh = __halves2half2(h0, h1);
            Qs[d * 32 + (jp ^ ((d & 7) << 2))] = *(unsigned*)&hh;
        }
        __syncthreads();   // Vt ready

#pragma unroll
        for (int ks = 0; ks < 4; ks++) {
            const int i0 = ks * 8 + lr;
            const int u0 = i0 ^ swz, u1 = (i0 + 4) ^ swz;
            const int K0 = kt * 64 + ks * 16 + 2 * lr;
            unsigned a0 = packh2(S[r0 * AS_LDS + K0] * invA,
                                 S[r0 * AS_LDS + K0 + 1] * invA);
            unsigned a1 = packh2(S[(r0 + 8) * AS_LDS + K0] * invB,
                                 S[(r0 + 8) * AS_LDS + K0 + 1] * invB);
            unsigned a2 = packh2(S[r0 * AS_LDS + K0 + 8] * invA,
                                 S[r0 * AS_LDS + K0 + 9] * invA);
            unsigned a3 = packh2(S[(r0 + 8) * AS_LDS + K0 + 8] * invB,
                                 S[(r0 + 8) * AS_LDS + K0 + 9] * invB);
#pragma unroll
            for (int nt = 0; nt < 4; nt++) {
                int cc = wn * 32 + nt * 8 + lq;     // dim column
                unsigned b0 = Qs[cc * 32 + u0];
                unsigned b1 = Qs[cc * 32 + u1];
                HMMA16816(o[nt], a0, a1, a2, a3, b0, b1);
            }
        }
        __syncthreads();   // all mma done before next staging overwrite
    }

    // residual add into x
    float* xb = x + ((size_t)b * SEQ + qt * 64) * DMODEL + h * HDIM;
#pragma unroll
    for (int nt = 0; nt < 4; nt++) {
        int col = wn * 32 + nt * 8 + lr * 2;
        xb[(size_t)r0 * DMODEL + col]           += o[nt][0];
        xb[(size_t)r0 * DMODEL + col + 1]       += o[nt][1];
        xb[(size_t)(r0 + 8) * DMODEL + col]     += o[nt][2];
        xb[(size_t)(r0 + 8) * DMODEL + col + 1] += o[nt][3];
    }
}

// ---------------- launch ----------------------------------------------------
extern "C" void kernel_launch(void* const* d_in, const int* in_sizes, int n_in,
                              void* d_out, int out_size)
{
    const float* x_in = (const float*)d_in[0];
    const float* Wq = (const float*)d_in[1];
    const float* bq = (const float*)d_in[2];
    const float* Wk = (const float*)d_in[3];
    const float* bk = (const float*)d_in[4];
    const float* Wv = (const float*)d_in[5];
    const float* bv = (const float*)d_in[6];
    const float* g1 = (const float*)d_in[7];
    const float* be1 = (const float*)d_in[8];
    const float* g2 = (const float*)d_in[9];
    const float* be2 = (const float*)d_in[10];
    const float* W0 = (const float*)d_in[11];
    const float* b0 = (const float*)d_in[12];
    const float* W1 = (const float*)d_in[13];
    const float* b1 = (const float*)d_in[14];

    float* x = (float*)d_out;

    void *p_xln, *p_q, *p_k, *p_v, *p_h1;
    void *p_wq, *p_wk, *p_wv, *p_w0, *p_w1;
    cudaGetSymbolAddress(&p_xln, g_xln);
    cudaGetSymbolAddress(&p_q, g_q);
    cudaGetSymbolAddress(&p_k, g_k);
    cudaGetSymbolAddress(&p_v, g_v);
    cudaGetSymbolAddress(&p_h1, g_h1);
    cudaGetSymbolAddress(&p_wq, g_wqT);
    cudaGetSymbolAddress(&p_wk, g_wkT);
    cudaGetSymbolAddress(&p_wv, g_wvT);
    cudaGetSymbolAddress(&p_w0, g_w0T);
    cudaGetSymbolAddress(&p_w1, g_w1T);
    __half* xln = (__half*)p_xln;
    __half* q = (__half*)p_q;
    __half* k = (__half*)p_k;
    __half* v = (__half*)p_v;
    __half* h1 = (__half*)p_h1;
    __half* wqT = (__half*)p_wq;
    __half* wkT = (__half*)p_wk;
    __half* wvT = (__half*)p_wv;
    __half* w0T = (__half*)p_w0;
    __half* w1T = (__half*)p_w1;

    cudaFuncSetAttribute(attn_kernel, cudaFuncAttributeMaxDynamicSharedMemorySize,
                         ATTN_SMEM_BYTES);
    cudaFuncSetAttribute(h_gemm_qkv_kernel, cudaFuncAttributeMaxDynamicSharedMemorySize,
                         HGEMM_SMEM_128);
    cudaFuncSetAttribute(h_gemm_kernel<4,1>, cudaFuncAttributeMaxDynamicSharedMemorySize,
                         HGEMM_SMEM_128);
    cudaFuncSetAttribute(h_gemm_kernel<2,2>, cudaFuncAttributeMaxDynamicSharedMemorySize,
                         HGEMM_SMEM_64);

    cudaMemcpyAsync(x, x_in, (size_t)NTOK * DMODEL * sizeof(float),
                    cudaMemcpyDeviceToDevice, 0);

    dim3 tb(32, 8);
    transpose_h_kernel<<<dim3(DMODEL/32, DMODEL/32), tb>>>(Wq, wqT, DMODEL, DMODEL);
    transpose_h_kernel<<<dim3(DMODEL/32, DMODEL/32), tb>>>(Wk, wkT, DMODEL, DMODEL);
    transpose_h_kernel<<<dim3(DMODEL/32, DMODEL/32), tb>>>(Wv, wvT, DMODEL, DMODEL);
    transpose_h_kernel<<<dim3(FFDIM/32, DMODEL/32), tb>>>(W0, w0T, DMODEL, FFDIM);
    transpose_h_kernel<<<dim3(DMODEL/32, FFDIM/32), tb>>>(W1, w1T, FFDIM, DMODEL);

    const dim3 gemmQKV(DMODEL / 128, NTOK / 128, 3);  // (6,16,3)
    const dim3 gemmFF1(FFDIM / 128, NTOK / 128);      // (24,16)
    const dim3 gemmFF2(DMODEL / 128, NTOK / 64);      // (6,32)
    const dim3 attnGrid(SEQ / 64, BATCH * NHEAD);     // (8,48)

    for (int blk = 0; blk < NBLOCKS; blk++) {
        ln_kernel<<<NTOK / 8, 256>>>(x, g1, be1, xln);
        h_gemm_qkv_kernel<<<gemmQKV, 256, HGEMM_SMEM_128>>>(
            xln, wqT, wkT, wvT, bq, bk, bv, q, k, v);
        attn_kernel<<<attnGrid, 256, ATTN_SMEM_BYTES>>>(q, k, v, x);
        ln_kernel<<<NTOK / 8, 256>>>(x, g2, be2, xln);
        h_gemm_kernel<4,1><<<gemmFF1, 256, HGEMM_SMEM_128>>>(
            xln, w0T, b0, (void*)h1, FFDIM, DMODEL);
        h_gemm_kernel<2,2><<<gemmFF2, 256, HGEMM_SMEM_64>>>(
            h1, w1T, b1, (void*)x, DMODEL, FFDIM);
    }
}

// round 9
// speedup vs baseline: 8.3662x; 1.2915x over previous
#include <cuda_runtime.h>
#include <cuda_fp16.h>
#include <math.h>
#include <stdint.h>

// Problem constants
#define BATCH 4
#define SEQ   512
#define DMODEL 768
#define FFDIM 3072
#define NHEAD 12
#define HDIM  64
#define NTOK  (BATCH*SEQ)          // 2048
#define NBLOCKS 12

// ---------------- scratch (device globals; no allocation allowed) -----------
__device__ __half g_xln[NTOK * DMODEL];
__device__ __half g_q  [NTOK * DMODEL];
__device__ __half g_k  [NTOK * DMODEL];
__device__ __half g_v  [NTOK * DMODEL];
__device__ __half g_vt [NTOK * DMODEL];   // per (b,h): [64 dims][512 tokens]
__device__ __half g_h1 [NTOK * FFDIM];
// fp16, TRANSPOSED weights: wt[n][k] = half(W[k][n])
__device__ __half g_wqT[DMODEL * DMODEL];
__device__ __half g_wkT[DMODEL * DMODEL];
__device__ __half g_wvT[DMODEL * DMODEL];
__device__ __half g_w0T[FFDIM * DMODEL];
__device__ __half g_w1T[DMODEL * FFDIM];

__device__ __forceinline__ void cpa16(unsigned dst, const void* src) {
    asm volatile("cp.async.cg.shared.global [%0], [%1], 16;\n" :: "r"(dst), "l"(src));
}
__device__ __forceinline__ void cpa_commit() {
    asm volatile("cp.async.commit_group;\n" ::: "memory");
}
template <int N>
__device__ __forceinline__ void cpa_wait() {
    asm volatile("cp.async.wait_group %0;\n" :: "n"(N) : "memory");
}
__device__ __forceinline__ unsigned smem_u32(const void* p) {
    unsigned r;
    asm("{ .reg .u64 t; cvta.to.shared.u64 t, %1; cvt.u32.u64 %0, t; }"
        : "=r"(r) : "l"(p));
    return r;
}
__device__ __forceinline__ unsigned packh2(float a, float b) {
    __half2 h = __floats2half2_rn(a, b);
    return *(unsigned*)&h;
}

#define HMMA16816(acc, a0, a1, a2, a3, b0, b1) \
    asm volatile( \
        "mma.sync.aligned.m16n8k16.row.col.f32.f16.f16.f32 " \
        "{%0,%1,%2,%3}, {%4,%5,%6,%7}, {%8,%9}, {%0,%1,%2,%3};" \
        : "+f"((acc)[0]), "+f"((acc)[1]), "+f"((acc)[2]), "+f"((acc)[3]) \
        : "r"(a0), "r"(a1), "r"(a2), "r"(a3), "r"(b0), "r"(b1))

// ---------------- transpose + fp16 convert (weights, once per launch) -------
__global__ __launch_bounds__(256) void transpose_h_kernel(
    const float* __restrict__ src, __half* __restrict__ dst, int R, int C)
{
    __shared__ float t[32][33];
    const int c0 = blockIdx.x * 32, r0 = blockIdx.y * 32;
    const int tx = threadIdx.x, ty = threadIdx.y;
#pragma unroll
    for (int i = 0; i < 4; i++)
        t[ty + 8 * i][tx] = src[(size_t)(r0 + ty + 8 * i) * C + c0 + tx];
    __syncthreads();
#pragma unroll
    for (int i = 0; i < 4; i++)
        dst[(size_t)(c0 + ty + 8 * i) * R + r0 + tx] = __float2half_rn(t[tx][ty + 8 * i]);
}

// ---------------- per-block V transpose: v[token][dim] -> vt[bh][dim][token]
__global__ __launch_bounds__(256) void transpose_v_kernel(
    const __half* __restrict__ v, __half* __restrict__ vt)
{
    __shared__ __half t[32][33];
    const int bh = blockIdx.z;
    const int b = bh / NHEAD, h = bh % NHEAD;
    const int t0 = blockIdx.x * 32;     // token tile
    const int d0 = blockIdx.y * 32;     // dim tile
    const int tx = threadIdx.x, ty = threadIdx.y;
#pragma unroll
    for (int i = 0; i < 4; i++)
        t[ty + 8 * i][tx] =
            v[((size_t)b * SEQ + t0 + ty + 8 * i) * DMODEL + h * HDIM + d0 + tx];
    __syncthreads();
#pragma unroll
    for (int i = 0; i < 4; i++)
        vt[(size_t)bh * HDIM * SEQ + (size_t)(d0 + ty + 8 * i) * SEQ + t0 + tx] =
            t[tx][ty + 8 * i];
}

// ---------------- LayerNorm: warp per row; outputs fp16 ---------------------
__global__ __launch_bounds__(256) void ln_kernel(
    const float* __restrict__ x, const float* __restrict__ g,
    const float* __restrict__ be, __half* __restrict__ y)
{
    const int wid = threadIdx.x >> 5, lane = threadIdx.x & 31;
    const int r = blockIdx.x * 8 + wid;
    const float* xr = x + (size_t)r * DMODEL;

    float4 v[6];
    float s = 0.f, s2 = 0.f;
#pragma unroll
    for (int i = 0; i < 6; i++) {
        v[i] = *(const float4*)(xr + (i * 32 + lane) * 4);
        s  += v[i].x + v[i].y + v[i].z + v[i].w;
        s2 += v[i].x * v[i].x + v[i].y * v[i].y + v[i].z * v[i].z + v[i].w * v[i].w;
    }
#pragma unroll
    for (int o = 16; o > 0; o >>= 1) {
        s  += __shfl_xor_sync(0xffffffffu, s,  o);
        s2 += __shfl_xor_sync(0xffffffffu, s2, o);
    }
    const float mu  = s  * (1.f / DMODEL);
    const float var = s2 * (1.f / DMODEL) - mu * mu;
    const float inv = rsqrtf(var + 1e-5f);
    __half* yr = y + (size_t)r * DMODEL;
#pragma unroll
    for (int i = 0; i < 6; i++) {
        const int col = (i * 32 + lane) * 4;
        float4 gg = *(const float4*)(g + col);
        float4 bb = *(const float4*)(be + col);
        unsigned p0 = packh2((v[i].x - mu) * inv * gg.x + bb.x,
                             (v[i].y - mu) * inv * gg.y + bb.y);
        unsigned p1 = packh2((v[i].z - mu) * inv * gg.z + bb.z,
                             (v[i].w - mu) * inv * gg.w + bb.w);
        uint2 o; o.x = p0; o.y = p1;
        *(uint2*)(yr + col) = o;
    }
}

// ===================== FP16 tensor-core GEMM (unchanged from R7) ============
#define BKH 64
#define NSTAGE 3

template <int MT, int MODE>
__device__ __forceinline__ void h_gemm_core(
    const __half* __restrict__ A, const __half* __restrict__ BT,
    const float* __restrict__ bias, void* __restrict__ Cv,
    int N, int K)
{
    constexpr int BMv  = MT * 32;
    constexpr int ASTG = BMv * 32;
    constexpr int BSTG = 128 * 32;

    extern __shared__ unsigned smemU[];
    unsigned* As = smemU;
    unsigned* Bs = smemU + NSTAGE * ASTG;
    const unsigned asBase = smem_u32(As);
    const unsigned bsBase = smem_u32(Bs);

    const int tid  = threadIdx.x;
    const int lane = tid & 31;
    const int wid  = tid >> 5;
    const int wm   = wid >> 2;
    const int wn   = wid & 3;
    const int rowBase = blockIdx.y * BMv;
    const int colBase = blockIdx.x * 128;
    const int lq = lane >> 2;
    const int lr = lane & 3;

    auto issue = [&](int c) {
        const int st = c % NSTAGE;
        const int k0 = c * BKH;
#pragma unroll
        for (int i = 0; i < MT; i++) {
            int fi = tid + i * 256;
            int r = fi >> 3, c8 = fi & 7;
            unsigned u = (unsigned)(c8 * 4) ^ (((unsigned)r & 7u) << 2);
            cpa16(asBase + (st * ASTG + r * 32 + u) * 4u,
                  A + (size_t)(rowBase + r) * K + k0 + c8 * 8);
        }
#pragma unroll
        for (int i = 0; i < 4; i++) {
            int fi = tid + i * 256;
            int r = fi >> 3, c8 = fi & 7;
            unsigned u = (unsigned)(c8 * 4) ^ (((unsigned)r & 7u) << 2);
            cpa16(bsBase + (st * BSTG + r * 32 + u) * 4u,
                  BT + (size_t)(colBase + r) * K + k0 + c8 * 8);
        }
    };

    float acc[MT][4][4];
#pragma unroll
    for (int i = 0; i < MT; i++)
#pragma unroll
        for (int j = 0; j < 4; j++)
#pragma unroll
            for (int t = 0; t < 4; t++) acc[i][j][t] = 0.f;

    const int nch = K / BKH;
    issue(0); cpa_commit();
    issue(1); cpa_commit();

    for (int c = 0; c < nch; c++) {
        cpa_wait<1>();
        __syncthreads();
        if (c + 2 < nch) issue(c + 2);
        cpa_commit();

        const unsigned* Ab = As + (c % NSTAGE) * ASTG;
        const unsigned* Bb = Bs + (c % NSTAGE) * BSTG;
        const unsigned swz = ((unsigned)lq & 7u) << 2;
#pragma unroll
        for (int ks = 0; ks < 4; ks++) {
            const int i0 = ks * 8 + lr;
            const int u0 = i0 ^ swz, u1 = (i0 + 4) ^ swz;
            unsigned af[MT][4];
#pragma unroll
            for (int mt = 0; mt < MT; mt++) {
                int r0 = wm * (MT * 16) + mt * 16 + lq;
                af[mt][0] = Ab[r0 * 32 + u0];
                af[mt][1] = Ab[(r0 + 8) * 32 + u0];
                af[mt][2] = Ab[r0 * 32 + u1];
                af[mt][3] = Ab[(r0 + 8) * 32 + u1];
            }
#pragma unroll
            for (int nt = 0; nt < 4; nt++) {
                int cc = wn * 32 + nt * 8 + lq;
                unsigned b0 = Bb[cc * 32 + u0];
                unsigned b1 = Bb[cc * 32 + u1];
#pragma unroll
                for (int mt = 0; mt < MT; mt++)
                    HMMA16816(acc[mt][nt], af[mt][0], af[mt][1], af[mt][2], af[mt][3], b0, b1);
            }
        }
        __syncthreads();
    }

#pragma unroll
    for (int mt = 0; mt < MT; mt++) {
        int row = rowBase + wm * (MT * 16) + mt * 16 + lq;
#pragma unroll
        for (int nt = 0; nt < 4; nt++) {
            int col = colBase + wn * 32 + nt * 8 + lr * 2;
            float b0 = bias[col], b1 = bias[col + 1];
            float v00 = acc[mt][nt][0] + b0;
            float v01 = acc[mt][nt][1] + b1;
            float v10 = acc[mt][nt][2] + b0;
            float v11 = acc[mt][nt][3] + b1;
            if (MODE == 1) {
                v00 = 0.5f * v00 * (1.0f + erff(v00 * 0.70710678118654752f));
                v01 = 0.5f * v01 * (1.0f + erff(v01 * 0.70710678118654752f));
                v10 = 0.5f * v10 * (1.0f + erff(v10 * 0.70710678118654752f));
                v11 = 0.5f * v11 * (1.0f + erff(v11 * 0.70710678118654752f));
            }
            if (MODE == 0 || MODE == 1) {
                __half* C = (__half*)Cv;
                *(unsigned*)(C + (size_t)row * N + col)       = packh2(v00, v01);
                *(unsigned*)(C + (size_t)(row + 8) * N + col) = packh2(v10, v11);
            } else {
                float* C = (float*)Cv;
                float2 c0 = *(const float2*)(C + (size_t)row * N + col);
                float2 c1 = *(const float2*)(C + (size_t)(row + 8) * N + col);
                c0.x += v00; c0.y += v01;
                c1.x += v10; c1.y += v11;
                *(float2*)(C + (size_t)row * N + col) = c0;
                *(float2*)(C + (size_t)(row + 8) * N + col) = c1;
            }
        }
    }
}

template <int MT, int MODE>
__global__ __launch_bounds__(256) void h_gemm_kernel(
    const __half* __restrict__ A, const __half* __restrict__ BT,
    const float* __restrict__ bias, void* __restrict__ C, int N, int K)
{
    h_gemm_core<MT, MODE>(A, BT, bias, C, N, K);
}

__global__ __launch_bounds__(256) void h_gemm_qkv_kernel(
    const __half* __restrict__ A,
    const __half* __restrict__ WqT, const __half* __restrict__ WkT,
    const __half* __restrict__ WvT,
    const float* __restrict__ bq, const float* __restrict__ bk,
    const float* __restrict__ bv,
    __half* __restrict__ q, __half* __restrict__ k, __half* __restrict__ v)
{
    const __half* BT; const float* bias; __half* C;
    if (blockIdx.z == 0)      { BT = WqT; bias = bq; C = q; }
    else if (blockIdx.z == 1) { BT = WkT; bias = bk; C = k; }
    else                      { BT = WvT; bias = bv; C = v; }
    h_gemm_core<4, 0>(A, BT, bias, (void*)C, DMODEL, DMODEL);
}

#define HGEMM_SMEM_128 (NSTAGE * (128*32 + 128*32) * 4)   // 98304
#define HGEMM_SMEM_64  (NSTAGE * (64*32  + 128*32) * 4)   // 73728

// ===================== Flash attention (fp16 mma, online softmax) ===========
// CTA: 128 q-rows x 512 keys (8 tiles of 64). 8 warps x 16 rows.
// Smem: Qs[128][32] u32 swizzled; Ks,Vs double-buffered [64][32] u32 each.
// vt supplies V^T tiles ([dim][token]) so B-fragments use GEMM index math.
#define FA_SMEM_BYTES ((4096 + 2*2048 + 2*2048) * 4)   // 49152

__global__ __launch_bounds__(256) void fattn_kernel(
    const __half* __restrict__ q, const __half* __restrict__ k,
    const __half* __restrict__ vt, float* __restrict__ x)
{
    extern __shared__ unsigned sm[];
    unsigned* Qs = sm;                 // [128][32]
    unsigned* Ks = sm + 4096;          // [2][64][32]
    unsigned* Vs = sm + 8192;          // [2][64][32]
    const unsigned qsB = smem_u32(Qs);
    const unsigned ksB = smem_u32(Ks);
    const unsigned vsB = smem_u32(Vs);

    const int tid = threadIdx.x;
    const int lane = tid & 31;
    const int wid = tid >> 5;          // 0..7 -> rows wid*16
    const int lq = lane >> 2;
    const int lr = lane & 3;
    const unsigned swz = (unsigned)lq << 2;

    const int qt = blockIdx.x;         // 0..3 (128-row q tiles)
    const int bh = blockIdx.y;
    const int b = bh / NHEAD, h = bh % NHEAD;

    const __half* qb  = q  + ((size_t)b * SEQ + qt * 128) * DMODEL + h * HDIM;
    const __half* kb  = k  + (size_t)b * SEQ * DMODEL + h * HDIM;
    const __half* vtb = vt + (size_t)bh * HDIM * SEQ;

    auto issueQ = [&]() {
#pragma unroll
        for (int i = 0; i < 4; i++) {
            int fi = tid + i * 256;               // 1024 chunks: 128 rows x 8
            int r = fi >> 3, c8 = fi & 7;
            unsigned u = (unsigned)(c8 * 4) ^ (((unsigned)r & 7u) << 2);
            cpa16(qsB + (r * 32 + u) * 4u, qb + (size_t)r * DMODEL + c8 * 8);
        }
    };
    auto issueK = [&](int kt) {
#pragma unroll
        for (int i = 0; i < 2; i++) {
            int fi = tid + i * 256;               // 512 chunks: 64 rows x 8
            int r = fi >> 3, c8 = fi & 7;
            unsigned u = (unsigned)(c8 * 4) ^ (((unsigned)r & 7u) << 2);
            cpa16(ksB + ((kt & 1) * 2048 + r * 32 + u) * 4u,
                  kb + (size_t)(kt * 64 + r) * DMODEL + c8 * 8);
        }
    };
    auto issueV = [&](int kt) {
#pragma unroll
        for (int i = 0; i < 2; i++) {
            int fi = tid + i * 256;               // 512 chunks: 64 dims x 8
            int r = fi >> 3, c8 = fi & 7;         // r = dim
            unsigned u = (unsigned)(c8 * 4) ^ (((unsigned)r & 7u) << 2);
            cpa16(vsB + ((kt & 1) * 2048 + r * 32 + u) * 4u,
                  vtb + (size_t)r * SEQ + kt * 64 + c8 * 8);
        }
    };

    issueQ(); issueK(0); issueV(0); cpa_commit();
    issueK(1); issueV(1); cpa_commit();

    float oacc[8][4];
#pragma unroll
    for (int nt = 0; nt < 8; nt++)
#pragma unroll
        for (int t = 0; t < 4; t++) oacc[nt][t] = 0.f;
    float mRun0 = -1e30f, mRun1 = -1e30f;
    float lRun0 = 0.f, lRun1 = 0.f;

    const int r0 = wid * 16 + lq;

    for (int kt = 0; kt < 8; kt++) {
        cpa_wait<1>();
        __syncthreads();

        // --- S tile = Q @ K^T (scaled later) ---
        float sacc[8][4];
#pragma unroll
        for (int nt = 0; nt < 8; nt++)
#pragma unroll
            for (int t = 0; t < 4; t++) sacc[nt][t] = 0.f;

        const unsigned* Kb = Ks + (kt & 1) * 2048;
        const unsigned* Vb = Vs + (kt & 1) * 2048;
#pragma unroll
        for (int ks = 0; ks < 4; ks++) {
            const int i0 = ks * 8 + lr;
            const int u0 = i0 ^ swz, u1 = (i0 + 4) ^ swz;
            unsigned a0 = Qs[r0 * 32 + u0];
            unsigned a1 = Qs[(r0 + 8) * 32 + u0];
            unsigned a2 = Qs[r0 * 32 + u1];
            unsigned a3 = Qs[(r0 + 8) * 32 + u1];
#pragma unroll
            for (int nt = 0; nt < 8; nt++) {
                int cc = nt * 8 + lq;
                unsigned b0 = Kb[cc * 32 + u0];
                unsigned b1 = Kb[cc * 32 + u1];
                HMMA16816(sacc[nt], a0, a1, a2, a3, b0, b1);
            }
        }

        // --- online softmax update (scale 1/8 folded in) ---
        float m0 = -1e30f, m1 = -1e30f;
#pragma unroll
        for (int nt = 0; nt < 8; nt++) {
            sacc[nt][0] *= 0.125f; sacc[nt][1] *= 0.125f;
            sacc[nt][2] *= 0.125f; sacc[nt][3] *= 0.125f;
            m0 = fmaxf(m0, fmaxf(sacc[nt][0], sacc[nt][1]));
            m1 = fmaxf(m1, fmaxf(sacc[nt][2], sacc[nt][3]));
        }
#pragma unroll
        for (int o = 1; o <= 2; o <<= 1) {
            m0 = fmaxf(m0, __shfl_xor_sync(0xffffffffu, m0, o));
            m1 = fmaxf(m1, __shfl_xor_sync(0xffffffffu, m1, o));
        }
        const float nm0 = fmaxf(mRun0, m0);
        const float nm1 = fmaxf(mRun1, m1);
        const float sc0 = __expf(mRun0 - nm0);
        const float sc1 = __expf(mRun1 - nm1);
        mRun0 = nm0; mRun1 = nm1;

        float lt0 = 0.f, lt1 = 0.f;
#pragma unroll
        for (int nt = 0; nt < 8; nt++) {
            sacc[nt][0] = __expf(sacc[nt][0] - nm0);
            sacc[nt][1] = __expf(sacc[nt][1] - nm0);
            sacc[nt][2] = __expf(sacc[nt][2] - nm1);
            sacc[nt][3] = __expf(sacc[nt][3] - nm1);
            lt0 += sacc[nt][0] + sacc[nt][1];
            lt1 += sacc[nt][2] + sacc[nt][3];
        }
        lRun0 = lRun0 * sc0 + lt0;
        lRun1 = lRun1 * sc1 + lt1;
#pragma unroll
        for (int nt = 0; nt < 8; nt++) {
            oacc[nt][0] *= sc0; oacc[nt][1] *= sc0;
            oacc[nt][2] *= sc1; oacc[nt][3] *= sc1;
        }

        // --- O += P @ V (P from registers; V^T tile as B) ---
#pragma unroll
        for (int kc = 0; kc < 4; kc++) {
            unsigned a0 = packh2(sacc[2 * kc][0],     sacc[2 * kc][1]);
            unsigned a1 = packh2(sacc[2 * kc][2],     sacc[2 * kc][3]);
            unsigned a2 = packh2(sacc[2 * kc + 1][0], sacc[2 * kc + 1][1]);
            unsigned a3 = packh2(sacc[2 * kc + 1][2], sacc[2 * kc + 1][3]);
            const int i0 = kc * 8 + lr;
            const int u0 = i0 ^ swz, u1 = (i0 + 4) ^ swz;
#pragma unroll
            for (int nt = 0; nt < 8; nt++) {
                int cc = nt * 8 + lq;               // dim row of V^T tile
                unsigned b0 = Vb[cc * 32 + u0];
                unsigned b1 = Vb[cc * 32 + u1];
                HMMA16816(oacc[nt], a0, a1, a2, a3, b0, b1);
            }
        }

        __syncthreads();       // stage kt&1 consumed
        if (kt + 2 < 8) { issueK(kt + 2); issueV(kt + 2); }
        cpa_commit();
    }

    // --- finalize: reduce l across the 4 lanes sharing a row, write out ---
#pragma unroll
    for (int o = 1; o <= 2; o <<= 1) {
        lRun0 += __shfl_xor_sync(0xffffffffu, lRun0, o);
        lRun1 += __shfl_xor_sync(0xffffffffu, lRun1, o);
    }
    const float inv0 = 1.f / lRun0;
    const float inv1 = 1.f / lRun1;

    float* xb = x + ((size_t)b * SEQ + qt * 128) * DMODEL + h * HDIM;
#pragma unroll
    for (int nt = 0; nt < 8; nt++) {
        int col = nt * 8 + lr * 2;
        float2 c0 = *(const float2*)(xb + (size_t)r0 * DMODEL + col);
        float2 c1 = *(const float2*)(xb + (size_t)(r0 + 8) * DMODEL + col);
        c0.x += oacc[nt][0] * inv0; c0.y += oacc[nt][1] * inv0;
        c1.x += oacc[nt][2] * inv1; c1.y += oacc[nt][3] * inv1;
        *(float2*)(xb + (size_t)r0 * DMODEL + col) = c0;
        *(float2*)(xb + (size_t)(r0 + 8) * DMODEL + col) = c1;
    }
}

// ---------------- launch ----------------------------------------------------
extern "C" void kernel_launch(void* const* d_in, const int* in_sizes, int n_in,
                              void* d_out, int out_size)
{
    const float* x_in = (const float*)d_in[0];
    const float* Wq = (const float*)d_in[1];
    const float* bq = (const float*)d_in[2];
    const float* Wk = (const float*)d_in[3];
    const float* bk = (const float*)d_in[4];
    const float* Wv = (const float*)d_in[5];
    const float* bv = (const float*)d_in[6];
    const float* g1 = (const float*)d_in[7];
    const float* be1 = (const float*)d_in[8];
    const float* g2 = (const float*)d_in[9];
    const float* be2 = (const float*)d_in[10];
    const float* W0 = (const float*)d_in[11];
    const float* b0 = (const float*)d_in[12];
    const float* W1 = (const float*)d_in[13];
    const float* b1 = (const float*)d_in[14];

    float* x = (float*)d_out;

    void *p_xln, *p_q, *p_k, *p_v, *p_vt, *p_h1;
    void *p_wq, *p_wk, *p_wv, *p_w0, *p_w1;
    cudaGetSymbolAddress(&p_xln, g_xln);
    cudaGetSymbolAddress(&p_q, g_q);
    cudaGetSymbolAddress(&p_k, g_k);
    cudaGetSymbolAddress(&p_v, g_v);
    cudaGetSymbolAddress(&p_vt, g_vt);
    cudaGetSymbolAddress(&p_h1, g_h1);
    cudaGetSymbolAddress(&p_wq, g_wqT);
    cudaGetSymbolAddress(&p_wk, g_wkT);
    cudaGetSymbolAddress(&p_wv, g_wvT);
    cudaGetSymbolAddress(&p_w0, g_w0T);
    cudaGetSymbolAddress(&p_w1, g_w1T);
    __half* xln = (__half*)p_xln;
    __half* q = (__half*)p_q;
    __half* k = (__half*)p_k;
    __half* v = (__half*)p_v;
    __half* vt = (__half*)p_vt;
    __half* h1 = (__half*)p_h1;
    __half* wqT = (__half*)p_wq;
    __half* wkT = (__half*)p_wk;
    __half* wvT = (__half*)p_wv;
    __half* w0T = (__half*)p_w0;
    __half* w1T = (__half*)p_w1;

    cudaFuncSetAttribute(fattn_kernel, cudaFuncAttributeMaxDynamicSharedMemorySize,
                         FA_SMEM_BYTES);
    cudaFuncSetAttribute(h_gemm_qkv_kernel, cudaFuncAttributeMaxDynamicSharedMemorySize,
                         HGEMM_SMEM_128);
    cudaFuncSetAttribute(h_gemm_kernel<4,1>, cudaFuncAttributeMaxDynamicSharedMemorySize,
                         HGEMM_SMEM_128);
    cudaFuncSetAttribute(h_gemm_kernel<2,2>, cudaFuncAttributeMaxDynamicSharedMemorySize,
                         HGEMM_SMEM_64);

    cudaMemcpyAsync(x, x_in, (size_t)NTOK * DMODEL * sizeof(float),
                    cudaMemcpyDeviceToDevice, 0);

    dim3 tb(32, 8);
    transpose_h_kernel<<<dim3(DMODEL/32, DMODEL/32), tb>>>(Wq, wqT, DMODEL, DMODEL);
    transpose_h_kernel<<<dim3(DMODEL/32, DMODEL/32), tb>>>(Wk, wkT, DMODEL, DMODEL);
    transpose_h_kernel<<<dim3(DMODEL/32, DMODEL/32), tb>>>(Wv, wvT, DMODEL, DMODEL);
    transpose_h_kernel<<<dim3(FFDIM/32, DMODEL/32), tb>>>(W0, w0T, DMODEL, FFDIM);
    transpose_h_kernel<<<dim3(DMODEL/32, FFDIM/32), tb>>>(W1, w1T, FFDIM, DMODEL);

    const dim3 gemmQKV(DMODEL / 128, NTOK / 128, 3);  // (6,16,3)
    const dim3 gemmFF1(FFDIM / 128, NTOK / 128);      // (24,16)
    const dim3 gemmFF2(DMODEL / 128, NTOK / 64);      // (6,32)
    const dim3 vtGrid(SEQ / 32, HDIM / 32, BATCH * NHEAD);  // (16,2,48)
    const dim3 attnGrid(SEQ / 128, BATCH * NHEAD);    // (4,48)

    for (int blk = 0; blk < NBLOCKS; blk++) {
        ln_kernel<<<NTOK / 8, 256>>>(x, g1, be1, xln);
        h_gemm_qkv_kernel<<<gemmQKV, 256, HGEMM_SMEM_128>>>(
            xln, wqT, wkT, wvT, bq, bk, bv, q, k, v);
        transpose_v_kernel<<<vtGrid, tb>>>(v, vt);
        fattn_kernel<<<attnGrid, 256, FA_SMEM_BYTES>>>(q, k, vt, x);
        ln_kernel<<<NTOK / 8, 256>>>(x, g2, be2, xln);
        h_gemm_kernel<4,1><<<gemmFF1, 256, HGEMM_SMEM_128>>>(
            xln, w0T, b0, (void*)h1, FFDIM, DMODEL);
        h_gemm_kernel<2,2><<<gemmFF2, 256, HGEMM_SMEM_64>>>(
            h1, w1T, b1, (void*)x, DMODEL, FFDIM);
    }
}

// round 10
// speedup vs baseline: 8.9078x; 1.0647x over previous
#include <cuda_runtime.h>
#include <cuda_fp16.h>
#include <math.h>
#include <stdint.h>

// Problem constants
#define BATCH 4
#define SEQ   512
#define DMODEL 768
#define FFDIM 3072
#define NHEAD 12
#define HDIM  64
#define NTOK  (BATCH*SEQ)          // 2048
#define NBLOCKS 12

// ---------------- scratch (device globals; no allocation allowed) -----------
__device__ __half g_xln[NTOK * DMODEL];
__device__ __half g_q  [NTOK * DMODEL];
__device__ __half g_k  [NTOK * DMODEL];
__device__ __half g_vt [NTOK * DMODEL];   // per (b,h): [64 dims][512 tokens]
__device__ __half g_h1 [NTOK * FFDIM];
// fp16, TRANSPOSED weights: wt[n][k] = half(W[k][n])
__device__ __half g_wqT[DMODEL * DMODEL];
__device__ __half g_wkT[DMODEL * DMODEL];
__device__ __half g_wvT[DMODEL * DMODEL];
__device__ __half g_w0T[FFDIM * DMODEL];
__device__ __half g_w1T[DMODEL * FFDIM];

__device__ __forceinline__ void cpa16(unsigned dst, const void* src) {
    asm volatile("cp.async.cg.shared.global [%0], [%1], 16;\n" :: "r"(dst), "l"(src));
}
__device__ __forceinline__ void cpa_commit() {
    asm volatile("cp.async.commit_group;\n" ::: "memory");
}
template <int N>
__device__ __forceinline__ void cpa_wait() {
    asm volatile("cp.async.wait_group %0;\n" :: "n"(N) : "memory");
}
__device__ __forceinline__ unsigned smem_u32(const void* p) {
    unsigned r;
    asm("{ .reg .u64 t; cvta.to.shared.u64 t, %1; cvt.u32.u64 %0, t; }"
        : "=r"(r) : "l"(p));
    return r;
}
__device__ __forceinline__ unsigned packh2(float a, float b) {
    __half2 h = __floats2half2_rn(a, b);
    return *(unsigned*)&h;
}
__device__ __forceinline__ void ldsm_x4(unsigned& r0, unsigned& r1,
                                        unsigned& r2, unsigned& r3, unsigned addr) {
    asm volatile("ldmatrix.sync.aligned.m8n8.x4.shared.b16 {%0,%1,%2,%3}, [%4];"
        : "=r"(r0), "=r"(r1), "=r"(r2), "=r"(r3) : "r"(addr));
}

#define HMMA16816(acc, a0, a1, a2, a3, b0, b1) \
    asm volatile( \
        "mma.sync.aligned.m16n8k16.row.col.f32.f16.f16.f32 " \
        "{%0,%1,%2,%3}, {%4,%5,%6,%7}, {%8,%9}, {%0,%1,%2,%3};" \
        : "+f"((acc)[0]), "+f"((acc)[1]), "+f"((acc)[2]), "+f"((acc)[3]) \
        : "r"(a0), "r"(a1), "r"(a2), "r"(a3), "r"(b0), "r"(b1))

// ---------------- transpose + fp16 convert (weights, once per launch) -------
__global__ __launch_bounds__(256) void transpose_h_kernel(
    const float* __restrict__ src, __half* __restrict__ dst, int R, int C)
{
    __shared__ float t[32][33];
    const int c0 = blockIdx.x * 32, r0 = blockIdx.y * 32;
    const int tx = threadIdx.x, ty = threadIdx.y;
#pragma unroll
    for (int i = 0; i < 4; i++)
        t[ty + 8 * i][tx] = src[(size_t)(r0 + ty + 8 * i) * C + c0 + tx];
    __syncthreads();
#pragma unroll
    for (int i = 0; i < 4; i++)
        dst[(size_t)(c0 + ty + 8 * i) * R + r0 + tx] = __float2half_rn(t[tx][ty + 8 * i]);
}

// ---------------- LayerNorm: warp per row; outputs fp16 ---------------------
__global__ __launch_bounds__(256) void ln_kernel(
    const float* __restrict__ x, const float* __restrict__ g,
    const float* __restrict__ be, __half* __restrict__ y)
{
    const int wid = threadIdx.x >> 5, lane = threadIdx.x & 31;
    const int r = blockIdx.x * 8 + wid;
    const float* xr = x + (size_t)r * DMODEL;

    float4 v[6];
    float s = 0.f, s2 = 0.f;
#pragma unroll
    for (int i = 0; i < 6; i++) {
        v[i] = *(const float4*)(xr + (i * 32 + lane) * 4);
        s  += v[i].x + v[i].y + v[i].z + v[i].w;
        s2 += v[i].x * v[i].x + v[i].y * v[i].y + v[i].z * v[i].z + v[i].w * v[i].w;
    }
#pragma unroll
    for (int o = 16; o > 0; o >>= 1) {
        s  += __shfl_xor_sync(0xffffffffu, s,  o);
        s2 += __shfl_xor_sync(0xffffffffu, s2, o);
    }
    const float mu  = s  * (1.f / DMODEL);
    const float var = s2 * (1.f / DMODEL) - mu * mu;
    const float inv = rsqrtf(var + 1e-5f);
    __half* yr = y + (size_t)r * DMODEL;
#pragma unroll
    for (int i = 0; i < 6; i++) {
        const int col = (i * 32 + lane) * 4;
        float4 gg = *(const float4*)(g + col);
        float4 bb = *(const float4*)(be + col);
        unsigned p0 = packh2((v[i].x - mu) * inv * gg.x + bb.x,
                             (v[i].y - mu) * inv * gg.y + bb.y);
        unsigned p1 = packh2((v[i].z - mu) * inv * gg.z + bb.z,
                             (v[i].w - mu) * inv * gg.w + bb.w);
        uint2 o; o.x = p0; o.y = p1;
        *(uint2*)(yr + col) = o;
    }
}

// ===================== FP16 tensor-core GEMM ================================
// C[M,N] = act(A[M,K] @ W[K,N] + bias); A fp16 [M][K], BT=W^T fp16 [N][K].
// CTA tile (MT*32)x128xBK64; 8 warps 2x4; warp tile (MT*16)x32; mma m16n8k16.
// Fragments via ldmatrix.x4 on XOR-swizzled smem.
// MODE 0: half store; 1: gelu half store; 2: float C += v; 4: V-transpose store.
#define BKH 64
#define NSTAGE 3

template <int MT, int MODE>
__device__ __forceinline__ void h_gemm_core(
    const __half* __restrict__ A, const __half* __restrict__ BT,
    const float* __restrict__ bias, void* __restrict__ Cv,
    int N, int K)
{
    constexpr int BMv  = MT * 32;
    constexpr int ASTG = BMv * 32;
    constexpr int BSTG = 128 * 32;

    extern __shared__ unsigned smemU[];
    unsigned* As = smemU;
    unsigned* Bs = smemU + NSTAGE * ASTG;
    const unsigned asBase = smem_u32(As);
    const unsigned bsBase = smem_u32(Bs);

    const int tid  = threadIdx.x;
    const int lane = tid & 31;
    const int wid  = tid >> 5;
    const int wm   = wid >> 2;
    const int wn   = wid & 3;
    const int rowBase = blockIdx.y * BMv;
    const int colBase = blockIdx.x * 128;
    const int lq = lane >> 2;
    const int lr = lane & 3;

    // ldmatrix lane-derived constants
    const int aRowOff = ((lane >> 3) & 1) * 8 + (lane & 7);
    const int aKhalf  = lane >> 4;                 // 0/1
    const int bRowOff = ((lane >> 4) & 1) * 8 + (lane & 7);
    const int bKhalf  = (lane >> 3) & 1;           // 0/1

    auto issue = [&](int c) {
        const int st = c % NSTAGE;
        const int k0 = c * BKH;
#pragma unroll
        for (int i = 0; i < MT; i++) {
            int fi = tid + i * 256;
            int r = fi >> 3, c8 = fi & 7;
            unsigned u = (unsigned)(c8 * 4) ^ (((unsigned)r & 7u) << 2);
            cpa16(asBase + (st * ASTG + r * 32 + u) * 4u,
                  A + (size_t)(rowBase + r) * K + k0 + c8 * 8);
        }
#pragma unroll
        for (int i = 0; i < 4; i++) {
            int fi = tid + i * 256;
            int r = fi >> 3, c8 = fi & 7;
            unsigned u = (unsigned)(c8 * 4) ^ (((unsigned)r & 7u) << 2);
            cpa16(bsBase + (st * BSTG + r * 32 + u) * 4u,
                  BT + (size_t)(colBase + r) * K + k0 + c8 * 8);
        }
    };

    float acc[MT][4][4];
#pragma unroll
    for (int i = 0; i < MT; i++)
#pragma unroll
        for (int j = 0; j < 4; j++)
#pragma unroll
            for (int t = 0; t < 4; t++) acc[i][j][t] = 0.f;

    const int nch = K / BKH;
    issue(0); cpa_commit();
    issue(1); cpa_commit();

    for (int c = 0; c < nch; c++) {
        cpa_wait<1>();
        __syncthreads();
        if (c + 2 < nch) issue(c + 2);
        cpa_commit();

        const unsigned stA = asBase + (unsigned)((c % NSTAGE) * ASTG) * 4u;
        const unsigned stB = bsBase + (unsigned)((c % NSTAGE) * BSTG) * 4u;
#pragma unroll
        for (int ks = 0; ks < 4; ks++) {
            unsigned af[MT][4];
#pragma unroll
            for (int mt = 0; mt < MT; mt++) {
                int r = wm * (MT * 16) + mt * 16 + aRowOff;
                int c2 = ks * 2 + aKhalf;
                unsigned off = (unsigned)(r * 32) + (((unsigned)(c2 * 4)) ^ (((unsigned)r & 7u) << 2));
                ldsm_x4(af[mt][0], af[mt][1], af[mt][2], af[mt][3], stA + off * 4u);
            }
            unsigned bf[4][2];
#pragma unroll
            for (int ntp = 0; ntp < 2; ntp++) {
                int nrow = wn * 32 + ntp * 16 + bRowOff;
                int c2 = ks * 2 + bKhalf;
                unsigned off = (unsigned)(nrow * 32) + (((unsigned)(c2 * 4)) ^ (((unsigned)nrow & 7u) << 2));
                ldsm_x4(bf[2 * ntp][0], bf[2 * ntp][1],
                        bf[2 * ntp + 1][0], bf[2 * ntp + 1][1], stB + off * 4u);
            }
#pragma unroll
            for (int nt = 0; nt < 4; nt++)
#pragma unroll
                for (int mt = 0; mt < MT; mt++)
                    HMMA16816(acc[mt][nt], af[mt][0], af[mt][1], af[mt][2], af[mt][3],
                              bf[nt][0], bf[nt][1]);
        }
        __syncthreads();
    }

#pragma unroll
    for (int mt = 0; mt < MT; mt++) {
        int row = rowBase + wm * (MT * 16) + mt * 16 + lq;
#pragma unroll
        for (int nt = 0; nt < 4; nt++) {
            int col = colBase + wn * 32 + nt * 8 + lr * 2;
            float b0 = bias[col], b1 = bias[col + 1];
            float v00 = acc[mt][nt][0] + b0;
            float v01 = acc[mt][nt][1] + b1;
            float v10 = acc[mt][nt][2] + b0;
            float v11 = acc[mt][nt][3] + b1;
            if (MODE == 1) {
                v00 = 0.5f * v00 * (1.0f + erff(v00 * 0.70710678118654752f));
                v01 = 0.5f * v01 * (1.0f + erff(v01 * 0.70710678118654752f));
                v10 = 0.5f * v10 * (1.0f + erff(v10 * 0.70710678118654752f));
                v11 = 0.5f * v11 * (1.0f + erff(v11 * 0.70710678118654752f));
            }
            if (MODE == 0 || MODE == 1) {
                __half* C = (__half*)Cv;
                *(unsigned*)(C + (size_t)row * N + col)       = packh2(v00, v01);
                *(unsigned*)(C + (size_t)(row + 8) * N + col) = packh2(v10, v11);
            } else if (MODE == 2) {
                float* C = (float*)Cv;
                float2 c0 = *(const float2*)(C + (size_t)row * N + col);
                float2 c1 = *(const float2*)(C + (size_t)(row + 8) * N + col);
                c0.x += v00; c0.y += v01;
                c1.x += v10; c1.y += v11;
                *(float2*)(C + (size_t)row * N + col) = c0;
                *(float2*)(C + (size_t)(row + 8) * N + col) = c1;
            } else {  // MODE 4: V transposed store -> vt[(b*DMODEL+col)*SEQ + tok]
                __half* C = (__half*)Cv;
                int bb = row >> 9;
                int tok = row & 511;
                size_t base = ((size_t)(bb * DMODEL + col)) * SEQ;
                C[base + tok]           = __float2half_rn(v00);
                C[base + SEQ + tok]     = __float2half_rn(v01);
                C[base + tok + 8]       = __float2half_rn(v10);
                C[base + SEQ + tok + 8] = __float2half_rn(v11);
            }
        }
    }
}

template <int MT, int MODE>
__global__ __launch_bounds__(256) void h_gemm_kernel(
    const __half* __restrict__ A, const __half* __restrict__ BT,
    const float* __restrict__ bias, void* __restrict__ C, int N, int K)
{
    h_gemm_core<MT, MODE>(A, BT, bias, C, N, K);
}

__global__ __launch_bounds__(256) void h_gemm_qkv_kernel(
    const __half* __restrict__ A,
    const __half* __restrict__ WqT, const __half* __restrict__ WkT,
    const __half* __restrict__ WvT,
    const float* __restrict__ bq, const float* __restrict__ bk,
    const float* __restrict__ bv,
    __half* __restrict__ q, __half* __restrict__ k, __half* __restrict__ vt)
{
    if (blockIdx.z == 0)      h_gemm_core<4, 0>(A, WqT, bq, (void*)q,  DMODEL, DMODEL);
    else if (blockIdx.z == 1) h_gemm_core<4, 0>(A, WkT, bk, (void*)k,  DMODEL, DMODEL);
    else                      h_gemm_core<4, 4>(A, WvT, bv, (void*)vt, DMODEL, DMODEL);
}

#define HGEMM_SMEM_128 (NSTAGE * (128*32 + 128*32) * 4)   // 98304
#define HGEMM_SMEM_64  (NSTAGE * (64*32  + 128*32) * 4)   // 73728

// ===================== Flash attention (fp16 mma, online softmax) ===========
#define FA_SMEM_BYTES ((4096 + 2*2048 + 2*2048) * 4)   // 49152

__global__ __launch_bounds__(256) void fattn_kernel(
    const __half* __restrict__ q, const __half* __restrict__ k,
    const __half* __restrict__ vt, float* __restrict__ x)
{
    extern __shared__ unsigned sm[];
    unsigned* Qs = sm;                 // [128][32]
    unsigned* Ks = sm + 4096;          // [2][64][32]
    unsigned* Vs = sm + 8192;          // [2][64][32]
    const unsigned qsB = smem_u32(Qs);
    const unsigned ksB = smem_u32(Ks);
    const unsigned vsB = smem_u32(Vs);

    const int tid = threadIdx.x;
    const int lane = tid & 31;
    const int wid = tid >> 5;
    const int lq = lane >> 2;
    const int lr = lane & 3;
    const unsigned swz = (unsigned)lq << 2;

    const int qt = blockIdx.x;
    const int bh = blockIdx.y;
    const int b = bh / NHEAD, h = bh % NHEAD;

    const __half* qb  = q  + ((size_t)b * SEQ + qt * 128) * DMODEL + h * HDIM;
    const __half* kb  = k  + (size_t)b * SEQ * DMODEL + h * HDIM;
    const __half* vtb = vt + (size_t)bh * HDIM * SEQ;

    auto issueQ = [&]() {
#pragma unroll
        for (int i = 0; i < 4; i++) {
            int fi = tid + i * 256;
            int r = fi >> 3, c8 = fi & 7;
            unsigned u = (unsigned)(c8 * 4) ^ (((unsigned)r & 7u) << 2);
            cpa16(qsB + (r * 32 + u) * 4u, qb + (size_t)r * DMODEL + c8 * 8);
        }
    };
    auto issueK = [&](int kt) {
#pragma unroll
        for (int i = 0; i < 2; i++) {
            int fi = tid + i * 256;
            int r = fi >> 3, c8 = fi & 7;
            unsigned u = (unsigned)(c8 * 4) ^ (((unsigned)r & 7u) << 2);
            cpa16(ksB + ((kt & 1) * 2048 + r * 32 + u) * 4u,
                  kb + (size_t)(kt * 64 + r) * DMODEL + c8 * 8);
        }
    };
    auto issueV = [&](int kt) {
#pragma unroll
        for (int i = 0; i < 2; i++) {
            int fi = tid + i * 256;
            int r = fi >> 3, c8 = fi & 7;
            unsigned u = (unsigned)(c8 * 4) ^ (((unsigned)r & 7u) << 2);
            cpa16(vsB + ((kt & 1) * 2048 + r * 32 + u) * 4u,
                  vtb + (size_t)r * SEQ + kt * 64 + c8 * 8);
        }
    };

    issueQ(); issueK(0); issueV(0); cpa_commit();
    issueK(1); issueV(1); cpa_commit();

    float oacc[8][4];
#pragma unroll
    for (int nt = 0; nt < 8; nt++)
#pragma unroll
        for (int t = 0; t < 4; t++) oacc[nt][t] = 0.f;
    float mRun0 = -1e30f, mRun1 = -1e30f;
    float lRun0 = 0.f, lRun1 = 0.f;

    const int r0 = wid * 16 + lq;

    for (int kt = 0; kt < 8; kt++) {
        cpa_wait<1>();
        __syncthreads();

        float sacc[8][4];
#pragma unroll
        for (int nt = 0; nt < 8; nt++)
#pragma unroll
            for (int t = 0; t < 4; t++) sacc[nt][t] = 0.f;

        const unsigned* Kb = Ks + (kt & 1) * 2048;
        const unsigned* Vb = Vs + (kt & 1) * 2048;
#pragma unroll
        for (int ks = 0; ks < 4; ks++) {
            const int i0 = ks * 8 + lr;
            const int u0 = i0 ^ swz, u1 = (i0 + 4) ^ swz;
            unsigned a0 = Qs[r0 * 32 + u0];
            unsigned a1 = Qs[(r0 + 8) * 32 + u0];
            unsigned a2 = Qs[r0 * 32 + u1];
            unsigned a3 = Qs[(r0 + 8) * 32 + u1];
#pragma unroll
            for (int nt = 0; nt < 8; nt++) {
                int cc = nt * 8 + lq;
                unsigned b0 = Kb[cc * 32 + u0];
                unsigned b1 = Kb[cc * 32 + u1];
                HMMA16816(sacc[nt], a0, a1, a2, a3, b0, b1);
            }
        }

        float m0 = -1e30f, m1 = -1e30f;
#pragma unroll
        for (int nt = 0; nt < 8; nt++) {
            sacc[nt][0] *= 0.125f; sacc[nt][1] *= 0.125f;
            sacc[nt][2] *= 0.125f; sacc[nt][3] *= 0.125f;
            m0 = fmaxf(m0, fmaxf(sacc[nt][0], sacc[nt][1]));
            m1 = fmaxf(m1, fmaxf(sacc[nt][2], sacc[nt][3]));
        }
#pragma unroll
        for (int o = 1; o <= 2; o <<= 1) {
            m0 = fmaxf(m0, __shfl_xor_sync(0xffffffffu, m0, o));
            m1 = fmaxf(m1, __shfl_xor_sync(0xffffffffu, m1, o));
        }
        const float nm0 = fmaxf(mRun0, m0);
        const float nm1 = fmaxf(mRun1, m1);
        const float sc0 = __expf(mRun0 - nm0);
        const float sc1 = __expf(mRun1 - nm1);
        mRun0 = nm0; mRun1 = nm1;

        float lt0 = 0.f, lt1 = 0.f;
#pragma unroll
        for (int nt = 0; nt < 8; nt++) {
            sacc[nt][0] = __expf(sacc[nt][0] - nm0);
            sacc[nt][1] = __expf(sacc[nt][1] - nm0);
            sacc[nt][2] = __expf(sacc[nt][2] - nm1);
            sacc[nt][3] = __expf(sacc[nt][3] - nm1);
            lt0 += sacc[nt][0] + sacc[nt][1];
            lt1 += sacc[nt][2] + sacc[nt][3];
        }
        lRun0 = lRun0 * sc0 + lt0;
        lRun1 = lRun1 * sc1 + lt1;
#pragma unroll
        for (int nt = 0; nt < 8; nt++) {
            oacc[nt][0] *= sc0; oacc[nt][1] *= sc0;
            oacc[nt][2] *= sc1; oacc[nt][3] *= sc1;
        }

#pragma unroll
        for (int kc = 0; kc < 4; kc++) {
            unsigned a0 = packh2(sacc[2 * kc][0],     sacc[2 * kc][1]);
            unsigned a1 = packh2(sacc[2 * kc][2],     sacc[2 * kc][3]);
            unsigned a2 = packh2(sacc[2 * kc + 1][0], sacc[2 * kc + 1][1]);
            unsigned a3 = packh2(sacc[2 * kc + 1][2], sacc[2 * kc + 1][3]);
            const int i0 = kc * 8 + lr;
            const int u0 = i0 ^ swz, u1 = (i0 + 4) ^ swz;
#pragma unroll
            for (int nt = 0; nt < 8; nt++) {
                int cc = nt * 8 + lq;
                unsigned b0 = Vb[cc * 32 + u0];
                unsigned b1 = Vb[cc * 32 + u1];
                HMMA16816(oacc[nt], a0, a1, a2, a3, b0, b1);
            }
        }

        __syncthreads();
        if (kt + 2 < 8) { issueK(kt + 2); issueV(kt + 2); }
        cpa_commit();
    }

#pragma unroll
    for (int o = 1; o <= 2; o <<= 1) {
        lRun0 += __shfl_xor_sync(0xffffffffu, lRun0, o);
        lRun1 += __shfl_xor_sync(0xffffffffu, lRun1, o);
    }
    const float inv0 = 1.f / lRun0;
    const float inv1 = 1.f / lRun1;

    float* xb = x + ((size_t)b * SEQ + qt * 128) * DMODEL + h * HDIM;
#pragma unroll
    for (int nt = 0; nt < 8; nt++) {
        int col = nt * 8 + lr * 2;
        float2 c0 = *(const float2*)(xb + (size_t)r0 * DMODEL + col);
        float2 c1 = *(const float2*)(xb + (size_t)(r0 + 8) * DMODEL + col);
        c0.x += oacc[nt][0] * inv0; c0.y += oacc[nt][1] * inv0;
        c1.x += oacc[nt][2] * inv1; c1.y += oacc[nt][3] * inv1;
        *(float2*)(xb + (size_t)r0 * DMODEL + col) = c0;
        *(float2*)(xb + (size_t)(r0 + 8) * DMODEL + col) = c1;
    }
}

// ---------------- launch ----------------------------------------------------
extern "C" void kernel_launch(void* const* d_in, const int* in_sizes, int n_in,
                              void* d_out, int out_size)
{
    const float* x_in = (const float*)d_in[0];
    const float* Wq = (const float*)d_in[1];
    const float* bq = (const float*)d_in[2];
    const float* Wk = (const float*)d_in[3];
    const float* bk = (const float*)d_in[4];
    const float* Wv = (const float*)d_in[5];
    const float* bv = (const float*)d_in[6];
    const float* g1 = (const float*)d_in[7];
    const float* be1 = (const float*)d_in[8];
    const float* g2 = (const float*)d_in[9];
    const float* be2 = (const float*)d_in[10];
    const float* W0 = (const float*)d_in[11];
    const float* b0 = (const float*)d_in[12];
    const float* W1 = (const float*)d_in[13];
    const float* b1 = (const float*)d_in[14];

    float* x = (float*)d_out;

    void *p_xln, *p_q, *p_k, *p_vt, *p_h1;
    void *p_wq, *p_wk, *p_wv, *p_w0, *p_w1;
    cudaGetSymbolAddress(&p_xln, g_xln);
    cudaGetSymbolAddress(&p_q, g_q);
    cudaGetSymbolAddress(&p_k, g_k);
    cudaGetSymbolAddress(&p_vt, g_vt);
    cudaGetSymbolAddress(&p_h1, g_h1);
    cudaGetSymbolAddress(&p_wq, g_wqT);
    cudaGetSymbolAddress(&p_wk, g_wkT);
    cudaGetSymbolAddress(&p_wv, g_wvT);
    cudaGetSymbolAddress(&p_w0, g_w0T);
    cudaGetSymbolAddress(&p_w1, g_w1T);
    __half* xln = (__half*)p_xln;
    __half* q = (__half*)p_q;
    __half* k = (__half*)p_k;
    __half* vt = (__half*)p_vt;
    __half* h1 = (__half*)p_h1;
    __half* wqT = (__half*)p_wq;
    __half* wkT = (__half*)p_wk;
    __half* wvT = (__half*)p_wv;
    __half* w0T = (__half*)p_w0;
    __half* w1T = (__half*)p_w1;

    cudaFuncSetAttribute(fattn_kernel, cudaFuncAttributeMaxDynamicSharedMemorySize,
                         FA_SMEM_BYTES);
    cudaFuncSetAttribute(h_gemm_qkv_kernel, cudaFuncAttributeMaxDynamicSharedMemorySize,
                         HGEMM_SMEM_128);
    cudaFuncSetAttribute(h_gemm_kernel<4,1>, cudaFuncAttributeMaxDynamicSharedMemorySize,
                         HGEMM_SMEM_128);
    cudaFuncSetAttribute(h_gemm_kernel<2,2>, cudaFuncAttributeMaxDynamicSharedMemorySize,
                         HGEMM_SMEM_64);

    cudaMemcpyAsync(x, x_in, (size_t)NTOK * DMODEL * sizeof(float),
                    cudaMemcpyDeviceToDevice, 0);

    dim3 tb(32, 8);
    transpose_h_kernel<<<dim3(DMODEL/32, DMODEL/32), tb>>>(Wq, wqT, DMODEL, DMODEL);
    transpose_h_kernel<<<dim3(DMODEL/32, DMODEL/32), tb>>>(Wk, wkT, DMODEL, DMODEL);
    transpose_h_kernel<<<dim3(DMODEL/32, DMODEL/32), tb>>>(Wv, wvT, DMODEL, DMODEL);
    transpose_h_kernel<<<dim3(FFDIM/32, DMODEL/32), tb>>>(W0, w0T, DMODEL, FFDIM);
    transpose_h_kernel<<<dim3(DMODEL/32, FFDIM/32), tb>>>(W1, w1T, FFDIM, DMODEL);

    const dim3 gemmQKV(DMODEL / 128, NTOK / 128, 3);  // (6,16,3)
    const dim3 gemmFF1(FFDIM / 128, NTOK / 128);      // (24,16)
    const dim3 gemmFF2(DMODEL / 128, NTOK / 64);      // (6,32)
    const dim3 attnGrid(SEQ / 128, BATCH * NHEAD);    // (4,48)

    for (int blk = 0; blk < NBLOCKS; blk++) {
        ln_kernel<<<NTOK / 8, 256>>>(x, g1, be1, xln);
        h_gemm_qkv_kernel<<<gemmQKV, 256, HGEMM_SMEM_128>>>(
            xln, wqT, wkT, wvT, bq, bk, bv, q, k, vt);
        fattn_kernel<<<attnGrid, 256, FA_SMEM_BYTES>>>(q, k, vt, x);
        ln_kernel<<<NTOK / 8, 256>>>(x, g2, be2, xln);
        h_gemm_kernel<4,1><<<gemmFF1, 256, HGEMM_SMEM_128>>>(
            xln, w0T, b0, (void*)h1, FFDIM, DMODEL);
        h_gemm_kernel<2,2><<<gemmFF2, 256, HGEMM_SMEM_64>>>(
            h1, w1T, b1, (void*)x, DMODEL, FFDIM);
    }
}